// round 2
// baseline (speedup 1.0000x reference)
#include <cuda_runtime.h>
#include <math.h>

// Problem constants
#define Bsz 64
#define Tsz 512
#define Vsz 256
#define Hsz 1024
#define G3  3072   // 3*H
#define WSTRIDE 1028                 // padded row stride (floats) -> conflict-free LDS
#define SCAN_SMEM ((24 * WSTRIDE + 2 * 32 * 64) * 4)   // 115072 bytes
#define NBLK 128

// ---------------- scratch (static __device__, no allocations) ----------------
__device__ float g_M0[(size_t)Vsz * G3];          // M0T[v][g] = emb[v].W_ih0[g] + b_ih0[g]
__device__ float g_gx[(size_t)Bsz * Tsz * G3];    // per-layer input-gate preacts
__device__ float g_y [(size_t)Bsz * Tsz * Hsz];   // layer output (reused)
__device__ float g_hA[Bsz * Hsz];
__device__ float g_hB[Bsz * Hsz];
__device__ unsigned g_bar;

__global__ void zero_bar_kernel() { g_bar = 0u; }

// ---------------- generic fp32 GEMM: C[M,N] = A[M,K] @ B[N,K]^T + bias[N] ----
// tile 64x64x16, 256 threads, 4x4 micro, k-major SMEM, register prefetch.
// remapA: A-row r -> (r/511)*512 + r%511  (skip last timestep for output GEMM)
__global__ __launch_bounds__(256) void gemm_tn_kernel(
    const float* __restrict__ A, const float* __restrict__ B,
    const float* __restrict__ bias, float* __restrict__ C,
    int M, int N, int K, int remapA)
{
    __shared__ float As[16][64];
    __shared__ float Bs[16][64];
    const int tid = threadIdx.x;
    const int m0 = blockIdx.y * 64;
    const int n0 = blockIdx.x * 64;
    const int ty = tid >> 4;
    const int tx = tid & 15;
    const int lr = tid >> 2;
    const int lk = (tid & 3) << 2;

    int arow = m0 + lr;
    if (remapA) arow = (arow / (Tsz - 1)) * Tsz + (arow % (Tsz - 1));
    const float* Ap = A + (size_t)arow * K + lk;
    const float* Bp = B + (size_t)(n0 + lr) * K + lk;

    float acc[4][4];
#pragma unroll
    for (int i = 0; i < 4; ++i)
#pragma unroll
        for (int j = 0; j < 4; ++j) acc[i][j] = 0.0f;

    float4 pa = *(const float4*)Ap;
    float4 pb = *(const float4*)Bp;
    const int nch = K >> 4;
    for (int c = 0; c < nch; ++c) {
        As[lk + 0][lr] = pa.x; As[lk + 1][lr] = pa.y; As[lk + 2][lr] = pa.z; As[lk + 3][lr] = pa.w;
        Bs[lk + 0][lr] = pb.x; Bs[lk + 1][lr] = pb.y; Bs[lk + 2][lr] = pb.z; Bs[lk + 3][lr] = pb.w;
        __syncthreads();
        if (c + 1 < nch) {
            pa = *(const float4*)(Ap + (c + 1) * 16);
            pb = *(const float4*)(Bp + (c + 1) * 16);
        }
#pragma unroll
        for (int k = 0; k < 16; ++k) {
            float4 av = *(const float4*)&As[k][ty << 2];
            float4 bv = *(const float4*)&Bs[k][tx << 2];
            acc[0][0] += av.x * bv.x; acc[0][1] += av.x * bv.y; acc[0][2] += av.x * bv.z; acc[0][3] += av.x * bv.w;
            acc[1][0] += av.y * bv.x; acc[1][1] += av.y * bv.y; acc[1][2] += av.y * bv.z; acc[1][3] += av.y * bv.w;
            acc[2][0] += av.z * bv.x; acc[2][1] += av.z * bv.y; acc[2][2] += av.z * bv.z; acc[2][3] += av.z * bv.w;
            acc[3][0] += av.w * bv.x; acc[3][1] += av.w * bv.y; acc[3][2] += av.w * bv.z; acc[3][3] += av.w * bv.w;
        }
        __syncthreads();
    }

#pragma unroll
    for (int i = 0; i < 4; ++i) {
        int crow = m0 + (ty << 2) + i;
        float* Cp = C + (size_t)crow * N + n0 + (tx << 2);
#pragma unroll
        for (int j = 0; j < 4; ++j)
            Cp[j] = acc[i][j] + bias[n0 + (tx << 2) + j];
    }
}

// ---------------- gx0 gather: gx0[bt, g] = M0T[X[bt], g]  (bias folded in) ---
__global__ __launch_bounds__(256) void gx0_fill_kernel(const int* __restrict__ X)
{
    size_t idx = (size_t)blockIdx.x * 256 + threadIdx.x;   // float4 index
    int bt = (int)(idx / (G3 / 4));
    int gq = (int)(idx % (G3 / 4));
    int tok = X[bt];
    float4 v = ((const float4*)g_M0)[(size_t)tok * (G3 / 4) + gq];
    ((float4*)g_gx)[idx] = v;
}

// ---------------- persistent GRU scan ---------------------------------------
// One launch per layer. 128 blocks x 256 threads, one block per SM (co-resident),
// block owns 8 h-columns. W_hh strip cached in SMEM once. Software grid barrier
// between steps. All h reads are .cg (L2-coherent across SMs).
__global__ __launch_bounds__(256) void gru_scan_kernel(
    const float* __restrict__ Whh, const float* __restrict__ bhh,
    const float* __restrict__ gx,  float* __restrict__ y,
    float* __restrict__ hA, float* __restrict__ hB)
{
    extern __shared__ float sm[];
    float* ws = sm;                       // [24][WSTRIDE]
    float* hsbase = sm + 24 * WSTRIDE;    // [2][32][64]

    const int tid = threadIdx.x;
    const int c0 = blockIdx.x << 3;
    const int ty = tid >> 3;              // batch row (and row+32)
    const int tx = tid & 7;               // h-column within block
    const int j  = c0 + tx;

    // Load weight strip (24 rows x 1024) once.
    for (int i = tid; i < 24 * 256; i += 256) {
        int r  = i >> 8;                  // 0..23  (gate*8 + col)
        int kq = i & 255;                 // float4 index within row
        int g = r >> 3, jj = r & 7;
        float4 v = *(const float4*)(Whh + (size_t)(g * Hsz + c0 + jj) * Hsz + kq * 4);
        float* wr = ws + r * WSTRIDE + kq * 4;
        wr[0] = v.x; wr[1] = v.y; wr[2] = v.z; wr[3] = v.w;
    }
    const float br = bhh[j];
    const float bz = bhh[Hsz + j];
    const float bn = bhh[2 * Hsz + j];
    __syncthreads();

    const float* wr_r = ws + tx * WSTRIDE;
    const float* wr_z = ws + (8 + tx) * WSTRIDE;
    const float* wr_n = ws + (16 + tx) * WSTRIDE;

    const int hrow = tid >> 3;            // 0..31
    const int kq   = tid & 7;             // float4 slot within 32-wide chunk

    for (int t = 0; t < Tsz; ++t) {
        const float* hin  = (t & 1) ? hB : hA;
        float*       hout = (t & 1) ? hA : hB;

        const float4* hp0 = (const float4*)(hin + (size_t)hrow * Hsz) + kq;
        const float4* hp1 = (const float4*)(hin + (size_t)(hrow + 32) * Hsz) + kq;

        float acc00 = 0.f, acc01 = 0.f, acc02 = 0.f;
        float acc10 = 0.f, acc11 = 0.f, acc12 = 0.f;

        float4 p0 = __ldcg(hp0);
        float4 p1 = __ldcg(hp1);
        for (int c = 0; c < 32; ++c) {
            float* hb = hsbase + (c & 1) * 2048;
            const int kb = kq << 2;
            hb[(kb + 0) * 64 + hrow] = p0.x; hb[(kb + 1) * 64 + hrow] = p0.y;
            hb[(kb + 2) * 64 + hrow] = p0.z; hb[(kb + 3) * 64 + hrow] = p0.w;
            hb[(kb + 0) * 64 + hrow + 32] = p1.x; hb[(kb + 1) * 64 + hrow + 32] = p1.y;
            hb[(kb + 2) * 64 + hrow + 32] = p1.z; hb[(kb + 3) * 64 + hrow + 32] = p1.w;
            __syncthreads();
            if (c + 1 < 32) {
                p0 = __ldcg(hp0 + (c + 1) * 8);
                p1 = __ldcg(hp1 + (c + 1) * 8);
            }
            const float* wrr = wr_r + c * 32;
            const float* wrz = wr_z + c * 32;
            const float* wrn = wr_n + c * 32;
#pragma unroll
            for (int k = 0; k < 32; ++k) {
                float h0v = hb[k * 64 + ty];
                float h1v = hb[k * 64 + ty + 32];
                float w_r = wrr[k];
                float w_z = wrz[k];
                float w_n = wrn[k];
                acc00 += h0v * w_r; acc01 += h0v * w_z; acc02 += h0v * w_n;
                acc10 += h1v * w_r; acc11 += h1v * w_z; acc12 += h1v * w_n;
            }
            // next iteration writes the other hs buffer; sync above protects reads
        }

        // gates + state update for rows ty and ty+32
#pragma unroll
        for (int r = 0; r < 2; ++r) {
            const int b = ty + r * 32;
            const float a0 = r ? acc10 : acc00;
            const float a1 = r ? acc11 : acc01;
            const float a2 = r ? acc12 : acc02;
            const size_t rowbt = (size_t)b * Tsz + t;
            const float* gxr = gx + rowbt * G3;
            const float xr = gxr[j];
            const float xz = gxr[Hsz + j];
            const float xn = gxr[2 * Hsz + j];
            const float rg = 1.0f / (1.0f + expf(-(xr + a0 + br)));
            const float zg = 1.0f / (1.0f + expf(-(xz + a1 + bz)));
            const float ng = tanhf(xn + rg * (a2 + bn));
            const float hold = __ldcg(hin + (size_t)b * Hsz + j);
            const float hnew = (1.0f - zg) * ng + zg * hold;
            hout[(size_t)b * Hsz + j] = hnew;
            y[rowbt * Hsz + j] = hnew;
        }

        // ---- grid barrier ----
        __syncthreads();
        if (tid == 0) {
            __threadfence();
            atomicAdd(&g_bar, 1u);
            const unsigned target = (unsigned)NBLK * (unsigned)(t + 1);
            unsigned v;
            do {
                asm volatile("ld.global.acquire.gpu.u32 %0, [%1];"
                             : "=r"(v) : "l"(&g_bar));
            } while (v < target);
        }
        __syncthreads();
    }
}

// ---------------- small float4 copy ------------------------------------------
__global__ void copy4_kernel(float* __restrict__ dst, const float* __restrict__ src, int n4)
{
    int i = blockIdx.x * blockDim.x + threadIdx.x;
    if (i < n4) ((float4*)dst)[i] = ((const float4*)src)[i];
}

// ---------------- launch ------------------------------------------------------
extern "C" void kernel_launch(void* const* d_in, const int* in_sizes, int n_in,
                              void* d_out, int out_size)
{
    const int*   X     = (const int*)d_in[0];
    const float* h0    = (const float*)d_in[1];
    const float* emb   = (const float*)d_in[2];
    const float* W_ih  = (const float*)d_in[3];
    const float* W_hh  = (const float*)d_in[4];
    const float* b_ih  = (const float*)d_in[5];
    const float* b_hh  = (const float*)d_in[6];
    const float* W_out = (const float*)d_in[7];
    const float* b_out = (const float*)d_in[8];
    float* out = (float*)d_out;

    float *pM0, *pgx, *py, *phA, *phB;
    cudaGetSymbolAddress((void**)&pM0, g_M0);
    cudaGetSymbolAddress((void**)&pgx, g_gx);
    cudaGetSymbolAddress((void**)&py,  g_y);
    cudaGetSymbolAddress((void**)&phA, g_hA);
    cudaGetSymbolAddress((void**)&phB, g_hB);

    cudaFuncSetAttribute(gru_scan_kernel,
                         cudaFuncAttributeMaxDynamicSharedMemorySize, SCAN_SMEM);

    // 1) M0T[v,g] = emb[v] . W_ih0[g] + b_ih0[g]
    {
        dim3 grid(G3 / 64, Vsz / 64);
        gemm_tn_kernel<<<grid, 256>>>(emb, W_ih, b_ih, pM0, Vsz, G3, Hsz, 0);
    }

    // 2) gx0 gather
    gx0_fill_kernel<<<(Bsz * Tsz * (G3 / 4)) / 256, 256>>>(X);

    // 3) layer-0 scan (single persistent launch)
    copy4_kernel<<<64, 256>>>(phA, h0, Bsz * Hsz / 4);
    zero_bar_kernel<<<1, 1>>>();
    gru_scan_kernel<<<NBLK, 256, SCAN_SMEM>>>(W_hh, b_hh, pgx, py, phA, phB);

    // 4) gx1 = y0 @ W_ih1^T + b_ih1
    {
        dim3 grid(G3 / 64, (Bsz * Tsz) / 64);
        gemm_tn_kernel<<<grid, 256>>>(py, W_ih + (size_t)G3 * Hsz, b_ih + G3, pgx,
                                      Bsz * Tsz, G3, Hsz, 0);
    }

    // 5) layer-1 scan
    copy4_kernel<<<64, 256>>>(phA, h0 + Bsz * Hsz, Bsz * Hsz / 4);
    zero_bar_kernel<<<1, 1>>>();
    gru_scan_kernel<<<NBLK, 256, SCAN_SMEM>>>(W_hh + (size_t)G3 * Hsz, b_hh + G3,
                                              pgx, py, phA, phB);

    // 6) logits for t < T-1
    {
        dim3 grid(Vsz / 64, (Bsz * (Tsz - 1)) / 64);
        gemm_tn_kernel<<<grid, 256>>>(py, W_out, b_out, out,
                                      Bsz * (Tsz - 1), Vsz, Hsz, 1);
    }
}

// round 3
// speedup vs baseline: 1.5945x; 1.5945x over previous
#include <cuda_runtime.h>
#include <math.h>

// Problem constants
#define Bsz 64
#define Tsz 512
#define Vsz 256
#define Hsz 1024
#define G3  3072   // 3*H
#define NBLK 128

#define WS_ROW 1028                       // padded W row stride (floats)
#define HS_ROW 132                        // padded h chunk row stride (floats)
#define HS_BUF (64 * HS_ROW)              // one h chunk buffer (floats)
#define SCAN_SMEM ((24 * WS_ROW + 2 * HS_BUF) * 4)   // 166272 bytes

// ---------------- scratch (static __device__, no allocations) ----------------
__device__ float g_M0[(size_t)Vsz * G3];
__device__ float g_gx[(size_t)Bsz * Tsz * G3];
__device__ float g_y [(size_t)Bsz * Tsz * Hsz];
__device__ float g_hA[Bsz * Hsz];
__device__ float g_hB[Bsz * Hsz];
__device__ unsigned g_bar;

__global__ void zero_bar_kernel() { g_bar = 0u; }

// ---------------- fp32 GEMM 64x64x16 (used for output GEMM w/ row remap) ----
__global__ __launch_bounds__(256) void gemm_tn_kernel(
    const float* __restrict__ A, const float* __restrict__ B,
    const float* __restrict__ bias, float* __restrict__ C,
    int M, int N, int K, int remapA)
{
    __shared__ float As[16][64];
    __shared__ float Bs[16][64];
    const int tid = threadIdx.x;
    const int m0 = blockIdx.y * 64;
    const int n0 = blockIdx.x * 64;
    const int ty = tid >> 4;
    const int tx = tid & 15;
    const int lr = tid >> 2;
    const int lk = (tid & 3) << 2;

    int arow = m0 + lr;
    if (remapA) arow = (arow / (Tsz - 1)) * Tsz + (arow % (Tsz - 1));
    const float* Ap = A + (size_t)arow * K + lk;
    const float* Bp = B + (size_t)(n0 + lr) * K + lk;

    float acc[4][4];
#pragma unroll
    for (int i = 0; i < 4; ++i)
#pragma unroll
        for (int j = 0; j < 4; ++j) acc[i][j] = 0.0f;

    float4 pa = *(const float4*)Ap;
    float4 pb = *(const float4*)Bp;
    const int nch = K >> 4;
    for (int c = 0; c < nch; ++c) {
        As[lk + 0][lr] = pa.x; As[lk + 1][lr] = pa.y; As[lk + 2][lr] = pa.z; As[lk + 3][lr] = pa.w;
        Bs[lk + 0][lr] = pb.x; Bs[lk + 1][lr] = pb.y; Bs[lk + 2][lr] = pb.z; Bs[lk + 3][lr] = pb.w;
        __syncthreads();
        if (c + 1 < nch) {
            pa = *(const float4*)(Ap + (c + 1) * 16);
            pb = *(const float4*)(Bp + (c + 1) * 16);
        }
#pragma unroll
        for (int k = 0; k < 16; ++k) {
            float4 av = *(const float4*)&As[k][ty << 2];
            float4 bv = *(const float4*)&Bs[k][tx << 2];
            acc[0][0] += av.x * bv.x; acc[0][1] += av.x * bv.y; acc[0][2] += av.x * bv.z; acc[0][3] += av.x * bv.w;
            acc[1][0] += av.y * bv.x; acc[1][1] += av.y * bv.y; acc[1][2] += av.y * bv.z; acc[1][3] += av.y * bv.w;
            acc[2][0] += av.z * bv.x; acc[2][1] += av.z * bv.y; acc[2][2] += av.z * bv.z; acc[2][3] += av.z * bv.w;
            acc[3][0] += av.w * bv.x; acc[3][1] += av.w * bv.y; acc[3][2] += av.w * bv.z; acc[3][3] += av.w * bv.w;
        }
        __syncthreads();
    }

#pragma unroll
    for (int i = 0; i < 4; ++i) {
        int crow = m0 + (ty << 2) + i;
        float* Cp = C + (size_t)crow * N + n0 + (tx << 2);
#pragma unroll
        for (int j = 0; j < 4; ++j)
            Cp[j] = acc[i][j] + bias[n0 + (tx << 2) + j];
    }
}

// ---------------- fp32 GEMM 128x128x16, 8x8 micro (gx1 + M0) ----------------
// C[M,N] = A[M,K] @ B[N,K]^T + bias[N]; M%128==0, N%128==0, K%16==0.
__global__ __launch_bounds__(256, 2) void gemm_tn_128(
    const float* __restrict__ A, const float* __restrict__ B,
    const float* __restrict__ bias, float* __restrict__ C,
    int M, int N, int K)
{
    __shared__ float As[16 * 128];
    __shared__ float Bs[16 * 128];
    const int tid = threadIdx.x;
    const int m0 = blockIdx.y * 128;
    const int n0 = blockIdx.x * 128;
    const int ty = tid >> 4;          // 0..15
    const int tx = tid & 15;          // 0..15
    const int lr = tid >> 1;          // 0..127
    const int lk = (tid & 1) << 3;    // 0 or 8

    const float* Ap = A + (size_t)(m0 + lr) * K + lk;
    const float* Bp = B + (size_t)(n0 + lr) * K + lk;

    float acc[8][8];
#pragma unroll
    for (int i = 0; i < 8; ++i)
#pragma unroll
        for (int j = 0; j < 8; ++j) acc[i][j] = 0.0f;

    float4 pa0 = *(const float4*)Ap;
    float4 pa1 = *(const float4*)(Ap + 4);
    float4 pb0 = *(const float4*)Bp;
    float4 pb1 = *(const float4*)(Bp + 4);

    const int nch = K >> 4;
    for (int c = 0; c < nch; ++c) {
        As[(lk + 0) * 128 + lr] = pa0.x; As[(lk + 1) * 128 + lr] = pa0.y;
        As[(lk + 2) * 128 + lr] = pa0.z; As[(lk + 3) * 128 + lr] = pa0.w;
        As[(lk + 4) * 128 + lr] = pa1.x; As[(lk + 5) * 128 + lr] = pa1.y;
        As[(lk + 6) * 128 + lr] = pa1.z; As[(lk + 7) * 128 + lr] = pa1.w;
        Bs[(lk + 0) * 128 + lr] = pb0.x; Bs[(lk + 1) * 128 + lr] = pb0.y;
        Bs[(lk + 2) * 128 + lr] = pb0.z; Bs[(lk + 3) * 128 + lr] = pb0.w;
        Bs[(lk + 4) * 128 + lr] = pb1.x; Bs[(lk + 5) * 128 + lr] = pb1.y;
        Bs[(lk + 6) * 128 + lr] = pb1.z; Bs[(lk + 7) * 128 + lr] = pb1.w;
        __syncthreads();
        if (c + 1 < nch) {
            pa0 = *(const float4*)(Ap + (c + 1) * 16);
            pa1 = *(const float4*)(Ap + (c + 1) * 16 + 4);
            pb0 = *(const float4*)(Bp + (c + 1) * 16);
            pb1 = *(const float4*)(Bp + (c + 1) * 16 + 4);
        }
#pragma unroll
        for (int k = 0; k < 16; ++k) {
            float4 a0 = *(const float4*)&As[k * 128 + (ty << 2)];
            float4 a1 = *(const float4*)&As[k * 128 + (ty << 2) + 64];
            float4 b0 = *(const float4*)&Bs[k * 128 + (tx << 2)];
            float4 b1 = *(const float4*)&Bs[k * 128 + (tx << 2) + 64];
            float av[8] = {a0.x, a0.y, a0.z, a0.w, a1.x, a1.y, a1.z, a1.w};
            float bv[8] = {b0.x, b0.y, b0.z, b0.w, b1.x, b1.y, b1.z, b1.w};
#pragma unroll
            for (int i = 0; i < 8; ++i)
#pragma unroll
                for (int j = 0; j < 8; ++j)
                    acc[i][j] += av[i] * bv[j];
        }
        __syncthreads();
    }

    float bb[8];
#pragma unroll
    for (int j = 0; j < 4; ++j) {
        bb[j]     = bias[n0 + (tx << 2) + j];
        bb[4 + j] = bias[n0 + (tx << 2) + 64 + j];
    }
#pragma unroll
    for (int i = 0; i < 8; ++i) {
        int row = m0 + (ty << 2) + (i & 3) + ((i >> 2) << 6);
        float* Cp = C + (size_t)row * N + n0 + (tx << 2);
        float4 v0 = make_float4(acc[i][0] + bb[0], acc[i][1] + bb[1],
                                acc[i][2] + bb[2], acc[i][3] + bb[3]);
        float4 v1 = make_float4(acc[i][4] + bb[4], acc[i][5] + bb[5],
                                acc[i][6] + bb[6], acc[i][7] + bb[7]);
        *(float4*)Cp = v0;
        *(float4*)(Cp + 64) = v1;
    }
}

// ---------------- gx0 gather: gx0[bt, g] = M0T[X[bt], g] ---------------------
__global__ __launch_bounds__(256) void gx0_fill_kernel(const int* __restrict__ X)
{
    size_t idx = (size_t)blockIdx.x * 256 + threadIdx.x;   // float4 index
    int bt = (int)(idx / (G3 / 4));
    int gq = (int)(idx % (G3 / 4));
    int tok = X[bt];
    float4 v = ((const float4*)g_M0)[(size_t)tok * (G3 / 4) + gq];
    ((float4*)g_gx)[idx] = v;
}

// ---------------- persistent GRU scan (vectorized LDS.128 inner loop) --------
__global__ __launch_bounds__(256) void gru_scan_kernel(
    const float* __restrict__ Whh, const float* __restrict__ bhh,
    const float* __restrict__ gx,  float* __restrict__ y,
    float* __restrict__ hA, float* __restrict__ hB, int t_base)
{
    extern __shared__ float sm[];
    float* ws = sm;                        // [24][WS_ROW]
    float* hs = sm + 24 * WS_ROW;          // [2][64][HS_ROW]

    const int tid = threadIdx.x;
    const int c0 = blockIdx.x << 3;        // first of 8 owned h-columns
    const int ty = tid >> 3;               // batch rows ty, ty+32
    const int tx = tid & 7;                // column within block
    const int j  = c0 + tx;

    // Load weight strip (rows = gate*8 + col), coalesced, once per layer.
    for (int i = tid; i < 24 * 256; i += 256) {
        int r  = i >> 8;                   // 0..23
        int kq = i & 255;                  // float4 index within row
        int g = r >> 3, jj = r & 7;
        float4 v = *(const float4*)(Whh + (size_t)(g * Hsz + c0 + jj) * Hsz + kq * 4);
        float* p = ws + r * WS_ROW + kq * 4;
        p[0] = v.x; p[1] = v.y; p[2] = v.z; p[3] = v.w;
    }
    const float br = bhh[j];
    const float bz = bhh[Hsz + j];
    const float bn = bhh[2 * Hsz + j];
    __syncthreads();

    const int w0 = tid >> 5;               // base h row for staging
    const int kq = tid & 31;               // float4 slot within 128-chunk
    const float* wr_r = ws + tx * WS_ROW;
    const float* wr_z = ws + (8 + tx) * WS_ROW;
    const float* wr_n = ws + (16 + tx) * WS_ROW;

    for (int t = 0; t < Tsz; ++t) {
        const float* hin  = (t & 1) ? hB : hA;
        float*       hout = (t & 1) ? hA : hB;

        float4 ph[8];
#pragma unroll
        for (int q = 0; q < 8; ++q)
            ph[q] = __ldcg((const float4*)(hin + (size_t)(w0 + 8 * q) * Hsz) + kq);
#pragma unroll
        for (int q = 0; q < 8; ++q) {
            float* p = hs + (w0 + 8 * q) * HS_ROW + kq * 4;
            p[0] = ph[q].x; p[1] = ph[q].y; p[2] = ph[q].z; p[3] = ph[q].w;
        }
        __syncthreads();

        float acc00 = 0.f, acc01 = 0.f, acc02 = 0.f;
        float acc10 = 0.f, acc11 = 0.f, acc12 = 0.f;

        for (int c = 0; c < 8; ++c) {
            if (c < 7) {
#pragma unroll
                for (int q = 0; q < 8; ++q)
                    ph[q] = __ldcg((const float4*)(hin + (size_t)(w0 + 8 * q) * Hsz
                                                   + (c + 1) * 128) + kq);
            }
            const float* hb  = hs + (c & 1) * HS_BUF;
            const float* h0p = hb + ty * HS_ROW;
            const float* h1p = hb + (ty + 32) * HS_ROW;
            const float* wrr = wr_r + c * 128;
            const float* wrz = wr_z + c * 128;
            const float* wrn = wr_n + c * 128;
#pragma unroll 4
            for (int k4 = 0; k4 < 32; ++k4) {
                const int k = k4 << 2;
                float4 a0 = *(const float4*)(h0p + k);
                float4 a1 = *(const float4*)(h1p + k);
                float4 q0 = *(const float4*)(wrr + k);
                float4 q1 = *(const float4*)(wrz + k);
                float4 q2 = *(const float4*)(wrn + k);
                acc00 = fmaf(a0.x, q0.x, acc00); acc01 = fmaf(a0.x, q1.x, acc01); acc02 = fmaf(a0.x, q2.x, acc02);
                acc10 = fmaf(a1.x, q0.x, acc10); acc11 = fmaf(a1.x, q1.x, acc11); acc12 = fmaf(a1.x, q2.x, acc12);
                acc00 = fmaf(a0.y, q0.y, acc00); acc01 = fmaf(a0.y, q1.y, acc01); acc02 = fmaf(a0.y, q2.y, acc02);
                acc10 = fmaf(a1.y, q0.y, acc10); acc11 = fmaf(a1.y, q1.y, acc11); acc12 = fmaf(a1.y, q2.y, acc12);
                acc00 = fmaf(a0.z, q0.z, acc00); acc01 = fmaf(a0.z, q1.z, acc01); acc02 = fmaf(a0.z, q2.z, acc02);
                acc10 = fmaf(a1.z, q0.z, acc10); acc11 = fmaf(a1.z, q1.z, acc11); acc12 = fmaf(a1.z, q2.z, acc12);
                acc00 = fmaf(a0.w, q0.w, acc00); acc01 = fmaf(a0.w, q1.w, acc01); acc02 = fmaf(a0.w, q2.w, acc02);
                acc10 = fmaf(a1.w, q0.w, acc10); acc11 = fmaf(a1.w, q1.w, acc11); acc12 = fmaf(a1.w, q2.w, acc12);
            }
            if (c < 7) {
#pragma unroll
                for (int q = 0; q < 8; ++q) {
                    float* p = hs + ((c + 1) & 1) * HS_BUF + (w0 + 8 * q) * HS_ROW + kq * 4;
                    p[0] = ph[q].x; p[1] = ph[q].y; p[2] = ph[q].z; p[3] = ph[q].w;
                }
                __syncthreads();
            }
        }

        // gates + state update for rows ty and ty+32
#pragma unroll
        for (int r = 0; r < 2; ++r) {
            const int b = ty + (r << 5);
            const float a0 = r ? acc10 : acc00;
            const float a1 = r ? acc11 : acc01;
            const float a2 = r ? acc12 : acc02;
            const size_t rowbt = (size_t)b * Tsz + t;
            const float* gxr = gx + rowbt * G3;
            const float xr = gxr[j];
            const float xz = gxr[Hsz + j];
            const float xn = gxr[2 * Hsz + j];
            const float rg = 1.0f / (1.0f + expf(-(xr + a0 + br)));
            const float zg = 1.0f / (1.0f + expf(-(xz + a1 + bz)));
            const float ng = tanhf(xn + rg * (a2 + bn));
            const float hold = __ldcg(hin + (size_t)b * Hsz + j);
            const float hnew = (1.0f - zg) * ng + zg * hold;
            hout[(size_t)b * Hsz + j] = hnew;
            y[rowbt * Hsz + j] = hnew;
        }

        // ---- grid barrier ----
        __syncthreads();
        if (tid == 0) {
            __threadfence();
            atomicAdd(&g_bar, 1u);
            const unsigned target = (unsigned)NBLK * (unsigned)(t_base + t + 1);
            unsigned v;
            do {
                asm volatile("ld.global.acquire.gpu.u32 %0, [%1];"
                             : "=r"(v) : "l"(&g_bar));
            } while (v < target);
        }
        __syncthreads();
    }
}

// ---------------- small float4 copy ------------------------------------------
__global__ void copy4_kernel(float* __restrict__ dst, const float* __restrict__ src, int n4)
{
    int i = blockIdx.x * blockDim.x + threadIdx.x;
    if (i < n4) ((float4*)dst)[i] = ((const float4*)src)[i];
}

// ---------------- launch ------------------------------------------------------
extern "C" void kernel_launch(void* const* d_in, const int* in_sizes, int n_in,
                              void* d_out, int out_size)
{
    const int*   X     = (const int*)d_in[0];
    const float* h0    = (const float*)d_in[1];
    const float* emb   = (const float*)d_in[2];
    const float* W_ih  = (const float*)d_in[3];
    const float* W_hh  = (const float*)d_in[4];
    const float* b_ih  = (const float*)d_in[5];
    const float* b_hh  = (const float*)d_in[6];
    const float* W_out = (const float*)d_in[7];
    const float* b_out = (const float*)d_in[8];
    float* out = (float*)d_out;

    float *pM0, *pgx, *py, *phA, *phB;
    cudaGetSymbolAddress((void**)&pM0, g_M0);
    cudaGetSymbolAddress((void**)&pgx, g_gx);
    cudaGetSymbolAddress((void**)&py,  g_y);
    cudaGetSymbolAddress((void**)&phA, g_hA);
    cudaGetSymbolAddress((void**)&phB, g_hB);

    cudaFuncSetAttribute(gru_scan_kernel,
                         cudaFuncAttributeMaxDynamicSharedMemorySize, SCAN_SMEM);

    // 0) reset grid barrier (once per replay; scan layers share one counter)
    zero_bar_kernel<<<1, 1>>>();

    // 1) M0T[v,g] = emb[v].W_ih0[g] + b_ih0[g]
    {
        dim3 grid(G3 / 128, Vsz / 128);
        gemm_tn_128<<<grid, 256>>>(emb, W_ih, b_ih, pM0, Vsz, G3, Hsz);
    }

    // 2) gx0 gather
    gx0_fill_kernel<<<(Bsz * Tsz * (G3 / 4)) / 256, 256>>>(X);

    // 3) layer-0 scan
    copy4_kernel<<<64, 256>>>(phA, h0, Bsz * Hsz / 4);
    gru_scan_kernel<<<NBLK, 256, SCAN_SMEM>>>(W_hh, b_hh, pgx, py, phA, phB, 0);

    // 4) gx1 = y0 @ W_ih1^T + b_ih1
    {
        dim3 grid(G3 / 128, (Bsz * Tsz) / 128);
        gemm_tn_128<<<grid, 256>>>(py, W_ih + (size_t)G3 * Hsz, b_ih + G3, pgx,
                                   Bsz * Tsz, G3, Hsz);
    }

    // 5) layer-1 scan (barrier counter continues from 512*NBLK)
    copy4_kernel<<<64, 256>>>(phA, h0 + Bsz * Hsz, Bsz * Hsz / 4);
    gru_scan_kernel<<<NBLK, 256, SCAN_SMEM>>>(W_hh + (size_t)G3 * Hsz, b_hh + G3,
                                              pgx, py, phA, phB, Tsz);

    // 6) logits for t < T-1 (row remap skips last timestep)
    {
        dim3 grid(Vsz / 64, (Bsz * (Tsz - 1)) / 64);
        gemm_tn_kernel<<<grid, 256>>>(py, W_out, b_out, out,
                                      Bsz * (Tsz - 1), Vsz, Hsz, 1);
    }
}

// round 4
// speedup vs baseline: 1.6076x; 1.0082x over previous
#include <cuda_runtime.h>
#include <math.h>

// Problem constants
#define Bsz 64
#define Tsz 512
#define Vsz 256
#define Hsz 1024
#define G3  3072   // 3*H
#define NBLK 128

#define WS_ROW 1028                       // padded W row stride (floats)
#define HS_ROW 132                        // padded h chunk row stride (floats)
#define HS_BUF (64 * HS_ROW)              // one h chunk buffer (floats)
#define SCAN_SMEM ((24 * WS_ROW + 2 * HS_BUF) * 4)   // 166272 bytes

typedef unsigned long long ull;

// packed fp32x2 FMA: d = a*b + d  (elementwise on 2 packed fp32 lanes)
__device__ __forceinline__ void ffma2(ull& d, ull a, ull b) {
    asm("fma.rn.f32x2 %0, %1, %2, %0;" : "+l"(d) : "l"(a), "l"(b));
}
__device__ __forceinline__ ull pack_rep(float v) {
    ull r; unsigned u = __float_as_uint(v);
    asm("mov.b64 %0, {%1, %1};" : "=l"(r) : "r"(u));
    return r;
}
__device__ __forceinline__ float2 unpack2(ull v) {
    float2 r;
    asm("mov.b64 {%0, %1}, %2;" : "=f"(r.x), "=f"(r.y) : "l"(v));
    return r;
}
__device__ __forceinline__ float hsum2(ull v) {
    float2 r = unpack2(v);
    return r.x + r.y;
}

// ---------------- scratch (static __device__, no allocations) ----------------
__device__ float g_M0[(size_t)Vsz * G3];
__device__ float g_gx[(size_t)Bsz * Tsz * G3];
__device__ float g_y [(size_t)Bsz * Tsz * Hsz];
__device__ float g_hA[Bsz * Hsz];
__device__ float g_hB[Bsz * Hsz];
__device__ unsigned g_bar;

__global__ void zero_bar_kernel() { g_bar = 0u; }

// ---------------- fp32 GEMM 64x64x16 (output GEMM w/ row remap), f32x2 ------
__global__ __launch_bounds__(256) void gemm_tn_kernel(
    const float* __restrict__ A, const float* __restrict__ B,
    const float* __restrict__ bias, float* __restrict__ C,
    int M, int N, int K, int remapA)
{
    __shared__ float As[16][64];
    __shared__ float Bs[16][64];
    const int tid = threadIdx.x;
    const int m0 = blockIdx.y * 64;
    const int n0 = blockIdx.x * 64;
    const int ty = tid >> 4;
    const int tx = tid & 15;
    const int lr = tid >> 2;
    const int lk = (tid & 3) << 2;

    int arow = m0 + lr;
    if (remapA) arow = (arow / (Tsz - 1)) * Tsz + (arow % (Tsz - 1));
    const float* Ap = A + (size_t)arow * K + lk;
    const float* Bp = B + (size_t)(n0 + lr) * K + lk;

    ull acc[4][2];   // [i][j-pair]: pairs (j0,j1),(j2,j3)
#pragma unroll
    for (int i = 0; i < 4; ++i) { acc[i][0] = 0ull; acc[i][1] = 0ull; }

    float4 pa = *(const float4*)Ap;
    float4 pb = *(const float4*)Bp;
    const int nch = K >> 4;
    for (int c = 0; c < nch; ++c) {
        As[lk + 0][lr] = pa.x; As[lk + 1][lr] = pa.y; As[lk + 2][lr] = pa.z; As[lk + 3][lr] = pa.w;
        Bs[lk + 0][lr] = pb.x; Bs[lk + 1][lr] = pb.y; Bs[lk + 2][lr] = pb.z; Bs[lk + 3][lr] = pb.w;
        __syncthreads();
        if (c + 1 < nch) {
            pa = *(const float4*)(Ap + (c + 1) * 16);
            pb = *(const float4*)(Bp + (c + 1) * 16);
        }
#pragma unroll
        for (int k = 0; k < 16; ++k) {
            float4 av = *(const float4*)&As[k][ty << 2];
            ulonglong2 bv = *(const ulonglong2*)&Bs[k][tx << 2];
            ull ap0 = pack_rep(av.x), ap1 = pack_rep(av.y);
            ull ap2 = pack_rep(av.z), ap3 = pack_rep(av.w);
            ffma2(acc[0][0], ap0, bv.x); ffma2(acc[0][1], ap0, bv.y);
            ffma2(acc[1][0], ap1, bv.x); ffma2(acc[1][1], ap1, bv.y);
            ffma2(acc[2][0], ap2, bv.x); ffma2(acc[2][1], ap2, bv.y);
            ffma2(acc[3][0], ap3, bv.x); ffma2(acc[3][1], ap3, bv.y);
        }
        __syncthreads();
    }

    float bb[4];
#pragma unroll
    for (int j = 0; j < 4; ++j) bb[j] = bias[n0 + (tx << 2) + j];
#pragma unroll
    for (int i = 0; i < 4; ++i) {
        int crow = m0 + (ty << 2) + i;
        float* Cp = C + (size_t)crow * N + n0 + (tx << 2);
        float2 v0 = unpack2(acc[i][0]);
        float2 v1 = unpack2(acc[i][1]);
        Cp[0] = v0.x + bb[0]; Cp[1] = v0.y + bb[1];
        Cp[2] = v1.x + bb[2]; Cp[3] = v1.y + bb[3];
    }
}

// ---------------- fp32 GEMM 128x128x16, 8x8 micro, f32x2 (gx1 + M0) ---------
__global__ __launch_bounds__(256, 2) void gemm_tn_128(
    const float* __restrict__ A, const float* __restrict__ B,
    const float* __restrict__ bias, float* __restrict__ C,
    int M, int N, int K)
{
    __shared__ float As[16 * 128];
    __shared__ float Bs[16 * 128];
    const int tid = threadIdx.x;
    const int m0 = blockIdx.y * 128;
    const int n0 = blockIdx.x * 128;
    const int ty = tid >> 4;          // 0..15
    const int tx = tid & 15;          // 0..15
    const int lr = tid >> 1;          // 0..127
    const int lk = (tid & 1) << 3;    // 0 or 8

    const float* Ap = A + (size_t)(m0 + lr) * K + lk;
    const float* Bp = B + (size_t)(n0 + lr) * K + lk;

    ull acc[8][4];   // [i][j-pair]: (j0,j1),(j2,j3),(j64,j65),(j66,j67)
#pragma unroll
    for (int i = 0; i < 8; ++i)
#pragma unroll
        for (int j = 0; j < 4; ++j) acc[i][j] = 0ull;

    float4 pa0 = *(const float4*)Ap;
    float4 pa1 = *(const float4*)(Ap + 4);
    float4 pb0 = *(const float4*)Bp;
    float4 pb1 = *(const float4*)(Bp + 4);

    const int nch = K >> 4;
    for (int c = 0; c < nch; ++c) {
        As[(lk + 0) * 128 + lr] = pa0.x; As[(lk + 1) * 128 + lr] = pa0.y;
        As[(lk + 2) * 128 + lr] = pa0.z; As[(lk + 3) * 128 + lr] = pa0.w;
        As[(lk + 4) * 128 + lr] = pa1.x; As[(lk + 5) * 128 + lr] = pa1.y;
        As[(lk + 6) * 128 + lr] = pa1.z; As[(lk + 7) * 128 + lr] = pa1.w;
        Bs[(lk + 0) * 128 + lr] = pb0.x; Bs[(lk + 1) * 128 + lr] = pb0.y;
        Bs[(lk + 2) * 128 + lr] = pb0.z; Bs[(lk + 3) * 128 + lr] = pb0.w;
        Bs[(lk + 4) * 128 + lr] = pb1.x; Bs[(lk + 5) * 128 + lr] = pb1.y;
        Bs[(lk + 6) * 128 + lr] = pb1.z; Bs[(lk + 7) * 128 + lr] = pb1.w;
        __syncthreads();
        if (c + 1 < nch) {
            pa0 = *(const float4*)(Ap + (c + 1) * 16);
            pa1 = *(const float4*)(Ap + (c + 1) * 16 + 4);
            pb0 = *(const float4*)(Bp + (c + 1) * 16);
            pb1 = *(const float4*)(Bp + (c + 1) * 16 + 4);
        }
#pragma unroll
        for (int k = 0; k < 16; ++k) {
            float4 a0 = *(const float4*)&As[k * 128 + (ty << 2)];
            float4 a1 = *(const float4*)&As[k * 128 + (ty << 2) + 64];
            ulonglong2 b0 = *(const ulonglong2*)&Bs[k * 128 + (tx << 2)];
            ulonglong2 b1 = *(const ulonglong2*)&Bs[k * 128 + (tx << 2) + 64];
            ull ap[8];
            ap[0] = pack_rep(a0.x); ap[1] = pack_rep(a0.y);
            ap[2] = pack_rep(a0.z); ap[3] = pack_rep(a0.w);
            ap[4] = pack_rep(a1.x); ap[5] = pack_rep(a1.y);
            ap[6] = pack_rep(a1.z); ap[7] = pack_rep(a1.w);
#pragma unroll
            for (int i = 0; i < 8; ++i) {
                ffma2(acc[i][0], ap[i], b0.x);
                ffma2(acc[i][1], ap[i], b0.y);
                ffma2(acc[i][2], ap[i], b1.x);
                ffma2(acc[i][3], ap[i], b1.y);
            }
        }
        __syncthreads();
    }

    float bb[8];
#pragma unroll
    for (int j = 0; j < 4; ++j) {
        bb[j]     = bias[n0 + (tx << 2) + j];
        bb[4 + j] = bias[n0 + (tx << 2) + 64 + j];
    }
#pragma unroll
    for (int i = 0; i < 8; ++i) {
        int row = m0 + (ty << 2) + (i & 3) + ((i >> 2) << 6);
        float* Cp = C + (size_t)row * N + n0 + (tx << 2);
        float2 c0 = unpack2(acc[i][0]);
        float2 c1 = unpack2(acc[i][1]);
        float2 c2 = unpack2(acc[i][2]);
        float2 c3 = unpack2(acc[i][3]);
        float4 v0 = make_float4(c0.x + bb[0], c0.y + bb[1], c1.x + bb[2], c1.y + bb[3]);
        float4 v1 = make_float4(c2.x + bb[4], c2.y + bb[5], c3.x + bb[6], c3.y + bb[7]);
        *(float4*)Cp = v0;
        *(float4*)(Cp + 64) = v1;
    }
}

// ---------------- gx0 gather: gx0[bt, g] = M0T[X[bt], g] ---------------------
__global__ __launch_bounds__(256) void gx0_fill_kernel(const int* __restrict__ X)
{
    size_t idx = (size_t)blockIdx.x * 256 + threadIdx.x;   // float4 index
    int bt = (int)(idx / (G3 / 4));
    int gq = (int)(idx % (G3 / 4));
    int tok = X[bt];
    float4 v = ((const float4*)g_M0)[(size_t)tok * (G3 / 4) + gq];
    ((float4*)g_gx)[idx] = v;
}

// ---------------- persistent GRU scan (f32x2, k-packed) ----------------------
__global__ __launch_bounds__(256) void gru_scan_kernel(
    const float* __restrict__ Whh, const float* __restrict__ bhh,
    const float* __restrict__ gx,  float* __restrict__ y,
    float* __restrict__ hA, float* __restrict__ hB, int t_base)
{
    extern __shared__ float sm[];
    float* ws = sm;                        // [24][WS_ROW]
    float* hs = sm + 24 * WS_ROW;          // [2][64][HS_ROW]

    const int tid = threadIdx.x;
    const int c0 = blockIdx.x << 3;        // first of 8 owned h-columns
    const int ty = tid >> 3;               // batch rows ty, ty+32
    const int tx = tid & 7;                // column within block
    const int j  = c0 + tx;

    // Load weight strip (rows = gate*8 + col), coalesced, once per layer.
    for (int i = tid; i < 24 * 256; i += 256) {
        int r  = i >> 8;                   // 0..23
        int kq = i & 255;                  // float4 index within row
        int g = r >> 3, jj = r & 7;
        float4 v = *(const float4*)(Whh + (size_t)(g * Hsz + c0 + jj) * Hsz + kq * 4);
        float* p = ws + r * WS_ROW + kq * 4;
        p[0] = v.x; p[1] = v.y; p[2] = v.z; p[3] = v.w;
    }
    const float br = bhh[j];
    const float bz = bhh[Hsz + j];
    const float bn = bhh[2 * Hsz + j];
    __syncthreads();

    const int w0 = tid >> 5;               // base h row for staging
    const int kq = tid & 31;               // float4 slot within 128-chunk
    const float* wr_r = ws + tx * WS_ROW;
    const float* wr_z = ws + (8 + tx) * WS_ROW;
    const float* wr_n = ws + (16 + tx) * WS_ROW;

    for (int t = 0; t < Tsz; ++t) {
        const float* hin  = (t & 1) ? hB : hA;
        float*       hout = (t & 1) ? hA : hB;

        float4 ph[8];
#pragma unroll
        for (int q = 0; q < 8; ++q)
            ph[q] = __ldcg((const float4*)(hin + (size_t)(w0 + 8 * q) * Hsz) + kq);
#pragma unroll
        for (int q = 0; q < 8; ++q) {
            float* p = hs + (w0 + 8 * q) * HS_ROW + kq * 4;
            p[0] = ph[q].x; p[1] = ph[q].y; p[2] = ph[q].z; p[3] = ph[q].w;
        }
        __syncthreads();

        ull acc00 = 0ull, acc01 = 0ull, acc02 = 0ull;
        ull acc10 = 0ull, acc11 = 0ull, acc12 = 0ull;

        for (int c = 0; c < 8; ++c) {
            if (c < 7) {
#pragma unroll
                for (int q = 0; q < 8; ++q)
                    ph[q] = __ldcg((const float4*)(hin + (size_t)(w0 + 8 * q) * Hsz
                                                   + (c + 1) * 128) + kq);
            }
            const float* hb  = hs + (c & 1) * HS_BUF;
            const float* h0p = hb + ty * HS_ROW;
            const float* h1p = hb + (ty + 32) * HS_ROW;
            const float* wrr = wr_r + c * 128;
            const float* wrz = wr_z + c * 128;
            const float* wrn = wr_n + c * 128;
#pragma unroll 4
            for (int k4 = 0; k4 < 32; ++k4) {
                const int k = k4 << 2;
                ulonglong2 a0 = *(const ulonglong2*)(h0p + k);
                ulonglong2 a1 = *(const ulonglong2*)(h1p + k);
                ulonglong2 q0 = *(const ulonglong2*)(wrr + k);
                ulonglong2 q1 = *(const ulonglong2*)(wrz + k);
                ulonglong2 q2 = *(const ulonglong2*)(wrn + k);
                ffma2(acc00, a0.x, q0.x); ffma2(acc00, a0.y, q0.y);
                ffma2(acc01, a0.x, q1.x); ffma2(acc01, a0.y, q1.y);
                ffma2(acc02, a0.x, q2.x); ffma2(acc02, a0.y, q2.y);
                ffma2(acc10, a1.x, q0.x); ffma2(acc10, a1.y, q0.y);
                ffma2(acc11, a1.x, q1.x); ffma2(acc11, a1.y, q1.y);
                ffma2(acc12, a1.x, q2.x); ffma2(acc12, a1.y, q2.y);
            }
            if (c < 7) {
#pragma unroll
                for (int q = 0; q < 8; ++q) {
                    float* p = hs + ((c + 1) & 1) * HS_BUF + (w0 + 8 * q) * HS_ROW + kq * 4;
                    p[0] = ph[q].x; p[1] = ph[q].y; p[2] = ph[q].z; p[3] = ph[q].w;
                }
                __syncthreads();
            }
        }

        const float s00 = hsum2(acc00), s01 = hsum2(acc01), s02 = hsum2(acc02);
        const float s10 = hsum2(acc10), s11 = hsum2(acc11), s12 = hsum2(acc12);

        // gates + state update for rows ty and ty+32
#pragma unroll
        for (int r = 0; r < 2; ++r) {
            const int b = ty + (r << 5);
            const float a0 = r ? s10 : s00;
            const float a1 = r ? s11 : s01;
            const float a2 = r ? s12 : s02;
            const size_t rowbt = (size_t)b * Tsz + t;
            const float* gxr = gx + rowbt * G3;
            const float xr = gxr[j];
            const float xz = gxr[Hsz + j];
            const float xn = gxr[2 * Hsz + j];
            const float rg = 1.0f / (1.0f + expf(-(xr + a0 + br)));
            const float zg = 1.0f / (1.0f + expf(-(xz + a1 + bz)));
            const float ng = tanhf(xn + rg * (a2 + bn));
            const float hold = __ldcg(hin + (size_t)b * Hsz + j);
            const float hnew = (1.0f - zg) * ng + zg * hold;
            hout[(size_t)b * Hsz + j] = hnew;
            y[rowbt * Hsz + j] = hnew;
        }

        // ---- grid barrier ----
        __syncthreads();
        if (tid == 0) {
            __threadfence();
            atomicAdd(&g_bar, 1u);
            const unsigned target = (unsigned)NBLK * (unsigned)(t_base + t + 1);
            unsigned v;
            do {
                asm volatile("ld.global.acquire.gpu.u32 %0, [%1];"
                             : "=r"(v) : "l"(&g_bar));
            } while (v < target);
        }
        __syncthreads();
    }
}

// ---------------- small float4 copy ------------------------------------------
__global__ void copy4_kernel(float* __restrict__ dst, const float* __restrict__ src, int n4)
{
    int i = blockIdx.x * blockDim.x + threadIdx.x;
    if (i < n4) ((float4*)dst)[i] = ((const float4*)src)[i];
}

// ---------------- launch ------------------------------------------------------
extern "C" void kernel_launch(void* const* d_in, const int* in_sizes, int n_in,
                              void* d_out, int out_size)
{
    const int*   X     = (const int*)d_in[0];
    const float* h0    = (const float*)d_in[1];
    const float* emb   = (const float*)d_in[2];
    const float* W_ih  = (const float*)d_in[3];
    const float* W_hh  = (const float*)d_in[4];
    const float* b_ih  = (const float*)d_in[5];
    const float* b_hh  = (const float*)d_in[6];
    const float* W_out = (const float*)d_in[7];
    const float* b_out = (const float*)d_in[8];
    float* out = (float*)d_out;

    float *pM0, *pgx, *py, *phA, *phB;
    cudaGetSymbolAddress((void**)&pM0, g_M0);
    cudaGetSymbolAddress((void**)&pgx, g_gx);
    cudaGetSymbolAddress((void**)&py,  g_y);
    cudaGetSymbolAddress((void**)&phA, g_hA);
    cudaGetSymbolAddress((void**)&phB, g_hB);

    cudaFuncSetAttribute(gru_scan_kernel,
                         cudaFuncAttributeMaxDynamicSharedMemorySize, SCAN_SMEM);

    // 0) reset grid barrier (once per replay; both scans share one counter)
    zero_bar_kernel<<<1, 1>>>();

    // 1) M0T[v,g] = emb[v].W_ih0[g] + b_ih0[g]
    {
        dim3 grid(G3 / 128, Vsz / 128);
        gemm_tn_128<<<grid, 256>>>(emb, W_ih, b_ih, pM0, Vsz, G3, Hsz);
    }

    // 2) gx0 gather
    gx0_fill_kernel<<<(Bsz * Tsz * (G3 / 4)) / 256, 256>>>(X);

    // 3) layer-0 scan
    copy4_kernel<<<64, 256>>>(phA, h0, Bsz * Hsz / 4);
    gru_scan_kernel<<<NBLK, 256, SCAN_SMEM>>>(W_hh, b_hh, pgx, py, phA, phB, 0);

    // 4) gx1 = y0 @ W_ih1^T + b_ih1
    {
        dim3 grid(G3 / 128, (Bsz * Tsz) / 128);
        gemm_tn_128<<<grid, 256>>>(py, W_ih + (size_t)G3 * Hsz, b_ih + G3, pgx,
                                   Bsz * Tsz, G3, Hsz);
    }

    // 5) layer-1 scan (barrier counter continues from 512*NBLK)
    copy4_kernel<<<64, 256>>>(phA, h0 + Bsz * Hsz, Bsz * Hsz / 4);
    gru_scan_kernel<<<NBLK, 256, SCAN_SMEM>>>(W_hh + (size_t)G3 * Hsz, b_hh + G3,
                                              pgx, py, phA, phB, Tsz);

    // 6) logits for t < T-1 (row remap skips last timestep)
    {
        dim3 grid(Vsz / 64, (Bsz * (Tsz - 1)) / 64);
        gemm_tn_kernel<<<grid, 256>>>(py, W_out, b_out, out,
                                      Bsz * (Tsz - 1), Vsz, Hsz, 1);
    }
}

// round 5
// speedup vs baseline: 1.6114x; 1.0024x over previous
#include <cuda_runtime.h>
#include <math.h>

// Problem constants
#define Bsz 64
#define Tsz 512
#define Vsz 256
#define Hsz 1024
#define G3  3072   // 3*H
#define NBLK 128

#define WS_ROW 1028                       // padded W row stride (floats)
#define HS_ROW 132                        // padded h chunk row stride (floats)
#define HS_BUF (64 * HS_ROW)              // one h chunk buffer (floats)
#define SCAN_SMEM ((24 * WS_ROW + 2 * HS_BUF) * 4)   // 166272 bytes

typedef unsigned long long ull;

// packed fp32x2 FMA: d = a*b + d  (elementwise on 2 packed fp32 lanes)
__device__ __forceinline__ void ffma2(ull& d, ull a, ull b) {
    asm("fma.rn.f32x2 %0, %1, %2, %0;" : "+l"(d) : "l"(a), "l"(b));
}
__device__ __forceinline__ ull pack_rep(float v) {
    ull r; unsigned u = __float_as_uint(v);
    asm("mov.b64 %0, {%1, %1};" : "=l"(r) : "r"(u));
    return r;
}
__device__ __forceinline__ float2 unpack2(ull v) {
    float2 r;
    asm("mov.b64 {%0, %1}, %2;" : "=f"(r.x), "=f"(r.y) : "l"(v));
    return r;
}
__device__ __forceinline__ float hsum2(ull v) {
    float2 r = unpack2(v);
    return r.x + r.y;
}

// ---------------- scratch (static __device__, no allocations) ----------------
__device__ float g_M0[(size_t)Vsz * G3];
__device__ float g_gx[(size_t)Bsz * Tsz * G3];
__device__ float g_y [(size_t)Bsz * Tsz * Hsz];
__device__ float g_hA[Bsz * Hsz];
__device__ float g_hB[Bsz * Hsz];
__device__ unsigned g_bar;

__global__ void zero_bar_kernel() { g_bar = 0u; }

// ---------------- fp32 GEMM 64x64x16 (output GEMM w/ row remap), f32x2 ------
__global__ __launch_bounds__(256) void gemm_tn_kernel(
    const float* __restrict__ A, const float* __restrict__ B,
    const float* __restrict__ bias, float* __restrict__ C,
    int M, int N, int K, int remapA)
{
    __shared__ float As[16][64];
    __shared__ float Bs[16][64];
    const int tid = threadIdx.x;
    const int m0 = blockIdx.y * 64;
    const int n0 = blockIdx.x * 64;
    const int ty = tid >> 4;
    const int tx = tid & 15;
    const int lr = tid >> 2;
    const int lk = (tid & 3) << 2;

    int arow = m0 + lr;
    if (remapA) arow = (arow / (Tsz - 1)) * Tsz + (arow % (Tsz - 1));
    const float* Ap = A + (size_t)arow * K + lk;
    const float* Bp = B + (size_t)(n0 + lr) * K + lk;

    ull acc[4][2];   // [i][j-pair]: pairs (j0,j1),(j2,j3)
#pragma unroll
    for (int i = 0; i < 4; ++i) { acc[i][0] = 0ull; acc[i][1] = 0ull; }

    float4 pa = *(const float4*)Ap;
    float4 pb = *(const float4*)Bp;
    const int nch = K >> 4;
    for (int c = 0; c < nch; ++c) {
        As[lk + 0][lr] = pa.x; As[lk + 1][lr] = pa.y; As[lk + 2][lr] = pa.z; As[lk + 3][lr] = pa.w;
        Bs[lk + 0][lr] = pb.x; Bs[lk + 1][lr] = pb.y; Bs[lk + 2][lr] = pb.z; Bs[lk + 3][lr] = pb.w;
        __syncthreads();
        if (c + 1 < nch) {
            pa = *(const float4*)(Ap + (c + 1) * 16);
            pb = *(const float4*)(Bp + (c + 1) * 16);
        }
#pragma unroll
        for (int k = 0; k < 16; ++k) {
            float4 av = *(const float4*)&As[k][ty << 2];
            ulonglong2 bv = *(const ulonglong2*)&Bs[k][tx << 2];
            ull ap0 = pack_rep(av.x), ap1 = pack_rep(av.y);
            ull ap2 = pack_rep(av.z), ap3 = pack_rep(av.w);
            ffma2(acc[0][0], ap0, bv.x); ffma2(acc[0][1], ap0, bv.y);
            ffma2(acc[1][0], ap1, bv.x); ffma2(acc[1][1], ap1, bv.y);
            ffma2(acc[2][0], ap2, bv.x); ffma2(acc[2][1], ap2, bv.y);
            ffma2(acc[3][0], ap3, bv.x); ffma2(acc[3][1], ap3, bv.y);
        }
        __syncthreads();
    }

    float bb[4];
#pragma unroll
    for (int j = 0; j < 4; ++j) bb[j] = bias[n0 + (tx << 2) + j];
#pragma unroll
    for (int i = 0; i < 4; ++i) {
        int crow = m0 + (ty << 2) + i;
        float* Cp = C + (size_t)crow * N + n0 + (tx << 2);
        float2 v0 = unpack2(acc[i][0]);
        float2 v1 = unpack2(acc[i][1]);
        Cp[0] = v0.x + bb[0]; Cp[1] = v0.y + bb[1];
        Cp[2] = v1.x + bb[2]; Cp[3] = v1.y + bb[3];
    }
}

// ---------------- fp32 GEMM 128x128x16, 8x8 micro, f32x2 (gx1 + M0) ---------
__global__ __launch_bounds__(256, 2) void gemm_tn_128(
    const float* __restrict__ A, const float* __restrict__ B,
    const float* __restrict__ bias, float* __restrict__ C,
    int M, int N, int K)
{
    __shared__ float As[16 * 128];
    __shared__ float Bs[16 * 128];
    const int tid = threadIdx.x;
    const int m0 = blockIdx.y * 128;
    const int n0 = blockIdx.x * 128;
    const int ty = tid >> 4;          // 0..15
    const int tx = tid & 15;          // 0..15
    const int lr = tid >> 1;          // 0..127
    const int lk = (tid & 1) << 3;    // 0 or 8

    const float* Ap = A + (size_t)(m0 + lr) * K + lk;
    const float* Bp = B + (size_t)(n0 + lr) * K + lk;

    ull acc[8][4];   // [i][j-pair]: (j0,j1),(j2,j3),(j64,j65),(j66,j67)
#pragma unroll
    for (int i = 0; i < 8; ++i)
#pragma unroll
        for (int j = 0; j < 4; ++j) acc[i][j] = 0ull;

    float4 pa0 = *(const float4*)Ap;
    float4 pa1 = *(const float4*)(Ap + 4);
    float4 pb0 = *(const float4*)Bp;
    float4 pb1 = *(const float4*)(Bp + 4);

    const int nch = K >> 4;
    for (int c = 0; c < nch; ++c) {
        As[(lk + 0) * 128 + lr] = pa0.x; As[(lk + 1) * 128 + lr] = pa0.y;
        As[(lk + 2) * 128 + lr] = pa0.z; As[(lk + 3) * 128 + lr] = pa0.w;
        As[(lk + 4) * 128 + lr] = pa1.x; As[(lk + 5) * 128 + lr] = pa1.y;
        As[(lk + 6) * 128 + lr] = pa1.z; As[(lk + 7) * 128 + lr] = pa1.w;
        Bs[(lk + 0) * 128 + lr] = pb0.x; Bs[(lk + 1) * 128 + lr] = pb0.y;
        Bs[(lk + 2) * 128 + lr] = pb0.z; Bs[(lk + 3) * 128 + lr] = pb0.w;
        Bs[(lk + 4) * 128 + lr] = pb1.x; Bs[(lk + 5) * 128 + lr] = pb1.y;
        Bs[(lk + 6) * 128 + lr] = pb1.z; Bs[(lk + 7) * 128 + lr] = pb1.w;
        __syncthreads();
        if (c + 1 < nch) {
            pa0 = *(const float4*)(Ap + (c + 1) * 16);
            pa1 = *(const float4*)(Ap + (c + 1) * 16 + 4);
            pb0 = *(const float4*)(Bp + (c + 1) * 16);
            pb1 = *(const float4*)(Bp + (c + 1) * 16 + 4);
        }
#pragma unroll
        for (int k = 0; k < 16; ++k) {
            float4 a0 = *(const float4*)&As[k * 128 + (ty << 2)];
            float4 a1 = *(const float4*)&As[k * 128 + (ty << 2) + 64];
            ulonglong2 b0 = *(const ulonglong2*)&Bs[k * 128 + (tx << 2)];
            ulonglong2 b1 = *(const ulonglong2*)&Bs[k * 128 + (tx << 2) + 64];
            ull ap[8];
            ap[0] = pack_rep(a0.x); ap[1] = pack_rep(a0.y);
            ap[2] = pack_rep(a0.z); ap[3] = pack_rep(a0.w);
            ap[4] = pack_rep(a1.x); ap[5] = pack_rep(a1.y);
            ap[6] = pack_rep(a1.z); ap[7] = pack_rep(a1.w);
#pragma unroll
            for (int i = 0; i < 8; ++i) {
                ffma2(acc[i][0], ap[i], b0.x);
                ffma2(acc[i][1], ap[i], b0.y);
                ffma2(acc[i][2], ap[i], b1.x);
                ffma2(acc[i][3], ap[i], b1.y);
            }
        }
        __syncthreads();
    }

    float bb[8];
#pragma unroll
    for (int j = 0; j < 4; ++j) {
        bb[j]     = bias[n0 + (tx << 2) + j];
        bb[4 + j] = bias[n0 + (tx << 2) + 64 + j];
    }
#pragma unroll
    for (int i = 0; i < 8; ++i) {
        int row = m0 + (ty << 2) + (i & 3) + ((i >> 2) << 6);
        float* Cp = C + (size_t)row * N + n0 + (tx << 2);
        float2 c0 = unpack2(acc[i][0]);
        float2 c1 = unpack2(acc[i][1]);
        float2 c2 = unpack2(acc[i][2]);
        float2 c3 = unpack2(acc[i][3]);
        float4 v0 = make_float4(c0.x + bb[0], c0.y + bb[1], c1.x + bb[2], c1.y + bb[3]);
        float4 v1 = make_float4(c2.x + bb[4], c2.y + bb[5], c3.x + bb[6], c3.y + bb[7]);
        *(float4*)Cp = v0;
        *(float4*)(Cp + 64) = v1;
    }
}

// ---------------- gx0 gather: gx0[bt, g] = M0T[X[bt], g] ---------------------
__global__ __launch_bounds__(256) void gx0_fill_kernel(const int* __restrict__ X)
{
    size_t idx = (size_t)blockIdx.x * 256 + threadIdx.x;   // float4 index
    int bt = (int)(idx / (G3 / 4));
    int gq = (int)(idx % (G3 / 4));
    int tok = X[bt];
    float4 v = ((const float4*)g_M0)[(size_t)tok * (G3 / 4) + gq];
    ((float4*)g_gx)[idx] = v;
}

// ---------------- persistent GRU scan (f32x2, k-packed) ----------------------
__global__ __launch_bounds__(256) void gru_scan_kernel(
    const float* __restrict__ Whh, const float* __restrict__ bhh,
    const float* __restrict__ gx,  float* __restrict__ y,
    float* __restrict__ hA, float* __restrict__ hB, int t_base)
{
    extern __shared__ float sm[];
    float* ws = sm;                        // [24][WS_ROW]
    float* hs = sm + 24 * WS_ROW;          // [2][64][HS_ROW]

    const int tid = threadIdx.x;
    const int c0 = blockIdx.x << 3;        // first of 8 owned h-columns
    const int ty = tid >> 3;               // batch rows ty, ty+32
    const int tx = tid & 7;                // column within block
    const int j  = c0 + tx;

    // Load weight strip (rows = gate*8 + col), coalesced, once per layer.
    for (int i = tid; i < 24 * 256; i += 256) {
        int r  = i >> 8;                   // 0..23
        int kq = i & 255;                  // float4 index within row
        int g = r >> 3, jj = r & 7;
        float4 v = *(const float4*)(Whh + (size_t)(g * Hsz + c0 + jj) * Hsz + kq * 4);
        float* p = ws + r * WS_ROW + kq * 4;
        p[0] = v.x; p[1] = v.y; p[2] = v.z; p[3] = v.w;
    }
    const float br = bhh[j];
    const float bz = bhh[Hsz + j];
    const float bn = bhh[2 * Hsz + j];
    __syncthreads();

    const int w0 = tid >> 5;               // base h row for staging
    const int kq = tid & 31;               // float4 slot within 128-chunk
    const float* wr_r = ws + tx * WS_ROW;
    const float* wr_z = ws + (8 + tx) * WS_ROW;
    const float* wr_n = ws + (16 + tx) * WS_ROW;

    for (int t = 0; t < Tsz; ++t) {
        const float* hin  = (t & 1) ? hB : hA;
        float*       hout = (t & 1) ? hA : hB;

        float4 ph[8];
#pragma unroll
        for (int q = 0; q < 8; ++q)
            ph[q] = __ldcg((const float4*)(hin + (size_t)(w0 + 8 * q) * Hsz) + kq);
#pragma unroll
        for (int q = 0; q < 8; ++q) {
            float* p = hs + (w0 + 8 * q) * HS_ROW + kq * 4;
            p[0] = ph[q].x; p[1] = ph[q].y; p[2] = ph[q].z; p[3] = ph[q].w;
        }
        __syncthreads();

        ull acc00 = 0ull, acc01 = 0ull, acc02 = 0ull;
        ull acc10 = 0ull, acc11 = 0ull, acc12 = 0ull;

        for (int c = 0; c < 8; ++c) {
            if (c < 7) {
#pragma unroll
                for (int q = 0; q < 8; ++q)
                    ph[q] = __ldcg((const float4*)(hin + (size_t)(w0 + 8 * q) * Hsz
                                                   + (c + 1) * 128) + kq);
            }
            const float* hb  = hs + (c & 1) * HS_BUF;
            const float* h0p = hb + ty * HS_ROW;
            const float* h1p = hb + (ty + 32) * HS_ROW;
            const float* wrr = wr_r + c * 128;
            const float* wrz = wr_z + c * 128;
            const float* wrn = wr_n + c * 128;
#pragma unroll 4
            for (int k4 = 0; k4 < 32; ++k4) {
                const int k = k4 << 2;
                ulonglong2 a0 = *(const ulonglong2*)(h0p + k);
                ulonglong2 a1 = *(const ulonglong2*)(h1p + k);
                ulonglong2 q0 = *(const ulonglong2*)(wrr + k);
                ulonglong2 q1 = *(const ulonglong2*)(wrz + k);
                ulonglong2 q2 = *(const ulonglong2*)(wrn + k);
                ffma2(acc00, a0.x, q0.x); ffma2(acc00, a0.y, q0.y);
                ffma2(acc01, a0.x, q1.x); ffma2(acc01, a0.y, q1.y);
                ffma2(acc02, a0.x, q2.x); ffma2(acc02, a0.y, q2.y);
                ffma2(acc10, a1.x, q0.x); ffma2(acc10, a1.y, q0.y);
                ffma2(acc11, a1.x, q1.x); ffma2(acc11, a1.y, q1.y);
                ffma2(acc12, a1.x, q2.x); ffma2(acc12, a1.y, q2.y);
            }
            if (c < 7) {
#pragma unroll
                for (int q = 0; q < 8; ++q) {
                    float* p = hs + ((c + 1) & 1) * HS_BUF + (w0 + 8 * q) * HS_ROW + kq * 4;
                    p[0] = ph[q].x; p[1] = ph[q].y; p[2] = ph[q].z; p[3] = ph[q].w;
                }
                __syncthreads();
            }
        }

        const float s00 = hsum2(acc00), s01 = hsum2(acc01), s02 = hsum2(acc02);
        const float s10 = hsum2(acc10), s11 = hsum2(acc11), s12 = hsum2(acc12);

        // gates + state update for rows ty and ty+32
#pragma unroll
        for (int r = 0; r < 2; ++r) {
            const int b = ty + (r << 5);
            const float a0 = r ? s10 : s00;
            const float a1 = r ? s11 : s01;
            const float a2 = r ? s12 : s02;
            const size_t rowbt = (size_t)b * Tsz + t;
            const float* gxr = gx + rowbt * G3;
            const float xr = gxr[j];
            const float xz = gxr[Hsz + j];
            const float xn = gxr[2 * Hsz + j];
            const float rg = 1.0f / (1.0f + expf(-(xr + a0 + br)));
            const float zg = 1.0f / (1.0f + expf(-(xz + a1 + bz)));
            const float ng = tanhf(xn + rg * (a2 + bn));
            const float hold = __ldcg(hin + (size_t)b * Hsz + j);
            const float hnew = (1.0f - zg) * ng + zg * hold;
            hout[(size_t)b * Hsz + j] = hnew;
            y[rowbt * Hsz + j] = hnew;
        }

        // ---- grid barrier ----
        __syncthreads();
        if (tid == 0) {
            __threadfence();
            atomicAdd(&g_bar, 1u);
            const unsigned target = (unsigned)NBLK * (unsigned)(t_base + t + 1);
            unsigned v;
            do {
                asm volatile("ld.global.acquire.gpu.u32 %0, [%1];"
                             : "=r"(v) : "l"(&g_bar));
            } while (v < target);
        }
        __syncthreads();
    }
}

// ---------------- small float4 copy ------------------------------------------
__global__ void copy4_kernel(float* __restrict__ dst, const float* __restrict__ src, int n4)
{
    int i = blockIdx.x * blockDim.x + threadIdx.x;
    if (i < n4) ((float4*)dst)[i] = ((const float4*)src)[i];
}

// ---------------- launch ------------------------------------------------------
extern "C" void kernel_launch(void* const* d_in, const int* in_sizes, int n_in,
                              void* d_out, int out_size)
{
    const int*   X     = (const int*)d_in[0];
    const float* h0    = (const float*)d_in[1];
    const float* emb   = (const float*)d_in[2];
    const float* W_ih  = (const float*)d_in[3];
    const float* W_hh  = (const float*)d_in[4];
    const float* b_ih  = (const float*)d_in[5];
    const float* b_hh  = (const float*)d_in[6];
    const float* W_out = (const float*)d_in[7];
    const float* b_out = (const float*)d_in[8];
    float* out = (float*)d_out;

    float *pM0, *pgx, *py, *phA, *phB;
    cudaGetSymbolAddress((void**)&pM0, g_M0);
    cudaGetSymbolAddress((void**)&pgx, g_gx);
    cudaGetSymbolAddress((void**)&py,  g_y);
    cudaGetSymbolAddress((void**)&phA, g_hA);
    cudaGetSymbolAddress((void**)&phB, g_hB);

    cudaFuncSetAttribute(gru_scan_kernel,
                         cudaFuncAttributeMaxDynamicSharedMemorySize, SCAN_SMEM);

    // 0) reset grid barrier (once per replay; both scans share one counter)
    zero_bar_kernel<<<1, 1>>>();

    // 1) M0T[v,g] = emb[v].W_ih0[g] + b_ih0[g]
    {
        dim3 grid(G3 / 128, Vsz / 128);
        gemm_tn_128<<<grid, 256>>>(emb, W_ih, b_ih, pM0, Vsz, G3, Hsz);
    }

    // 2) gx0 gather
    gx0_fill_kernel<<<(Bsz * Tsz * (G3 / 4)) / 256, 256>>>(X);

    // 3) layer-0 scan
    copy4_kernel<<<64, 256>>>(phA, h0, Bsz * Hsz / 4);
    gru_scan_kernel<<<NBLK, 256, SCAN_SMEM>>>(W_hh, b_hh, pgx, py, phA, phB, 0);

    // 4) gx1 = y0 @ W_ih1^T + b_ih1
    {
        dim3 grid(G3 / 128, (Bsz * Tsz) / 128);
        gemm_tn_128<<<grid, 256>>>(py, W_ih + (size_t)G3 * Hsz, b_ih + G3, pgx,
                                   Bsz * Tsz, G3, Hsz);
    }

    // 5) layer-1 scan (barrier counter continues from 512*NBLK)
    copy4_kernel<<<64, 256>>>(phA, h0 + Bsz * Hsz, Bsz * Hsz / 4);
    gru_scan_kernel<<<NBLK, 256, SCAN_SMEM>>>(W_hh + (size_t)G3 * Hsz, b_hh + G3,
                                              pgx, py, phA, phB, Tsz);

    // 6) logits for t < T-1 (row remap skips last timestep)
    {
        dim3 grid(Vsz / 64, (Bsz * (Tsz - 1)) / 64);
        gemm_tn_kernel<<<grid, 256>>>(py, W_out, b_out, out,
                                      Bsz * (Tsz - 1), Vsz, Hsz, 1);
    }
}

// round 6
// speedup vs baseline: 3.0666x; 1.9030x over previous
#include <cuda_runtime.h>
#include <cuda_bf16.h>
#include <math.h>

// Problem constants
#define Bsz 64
#define Tsz 512
#define Vsz 256
#define Hsz 1024
#define G3  3072   // 3*H
#define NBLK 128

#define SWPAD 1032       // W strip row stride (bf16) -> ldmatrix conflict-free
#define SHPAD 136        // h chunk row stride (bf16)
#define SCAN_SMEM_B ((24*SWPAD*2 + 2*64*SHPAD*2)*2 + 64*25*4)   // 175104 B

typedef unsigned long long ull;

// ---------------- mma.sync helpers ------------------------------------------
__device__ __forceinline__ void mma_bf16(float* c, const unsigned* a, const unsigned* b) {
    asm volatile(
        "mma.sync.aligned.m16n8k16.row.col.f32.bf16.bf16.f32 "
        "{%0,%1,%2,%3}, {%4,%5,%6,%7}, {%8,%9}, {%0,%1,%2,%3};\n"
        : "+f"(c[0]), "+f"(c[1]), "+f"(c[2]), "+f"(c[3])
        : "r"(a[0]), "r"(a[1]), "r"(a[2]), "r"(a[3]), "r"(b[0]), "r"(b[1]));
}
__device__ __forceinline__ void ldsm4(unsigned* r, const void* p) {
    unsigned a = (unsigned)__cvta_generic_to_shared(p);
    asm volatile("ldmatrix.sync.aligned.m8n8.x4.shared.b16 {%0,%1,%2,%3}, [%4];"
                 : "=r"(r[0]), "=r"(r[1]), "=r"(r[2]), "=r"(r[3]) : "r"(a));
}
__device__ __forceinline__ unsigned pack_bf16x2(__nv_bfloat16 a, __nv_bfloat16 b) {
    __nv_bfloat162 t; t.x = a; t.y = b;
    return *(unsigned*)&t;
}

// packed fp32x2 FMA (kept for the fp32 M0 GEMM)
__device__ __forceinline__ void ffma2(ull& d, ull a, ull b) {
    asm("fma.rn.f32x2 %0, %1, %2, %0;" : "+l"(d) : "l"(a), "l"(b));
}
__device__ __forceinline__ ull pack_rep(float v) {
    ull r; unsigned u = __float_as_uint(v);
    asm("mov.b64 %0, {%1, %1};" : "=l"(r) : "r"(u));
    return r;
}
__device__ __forceinline__ float2 unpack2(ull v) {
    float2 r;
    asm("mov.b64 {%0, %1}, %2;" : "=f"(r.x), "=f"(r.y) : "l"(v));
    return r;
}

// ---------------- scratch (static __device__, no allocations) ----------------
__device__ float g_M0[(size_t)Vsz * G3];
__device__ float g_gx[(size_t)Bsz * Tsz * G3];
__device__ __nv_bfloat16 g_yHi[(size_t)Bsz * Tsz * Hsz];
__device__ __nv_bfloat16 g_yLo[(size_t)Bsz * Tsz * Hsz];
__device__ float g_hFA[Bsz * Hsz];
__device__ float g_hFB[Bsz * Hsz];
__device__ __nv_bfloat16 g_hHiA[Bsz * Hsz], g_hHiB[Bsz * Hsz];
__device__ __nv_bfloat16 g_hLoA[Bsz * Hsz], g_hLoB[Bsz * Hsz];
__device__ unsigned g_bar;

__global__ void zero_bar_kernel() { g_bar = 0u; }

// ---------------- h0 init: fp32 copy + bf16 hi/lo split ----------------------
__global__ __launch_bounds__(256) void hinit_kernel(
    const float* __restrict__ src, float* __restrict__ hf,
    __nv_bfloat16* __restrict__ hhi, __nv_bfloat16* __restrict__ hlo)
{
    int i = blockIdx.x * 256 + threadIdx.x;
    float f = src[i];
    hf[i] = f;
    __nv_bfloat16 h = __float2bfloat16(f);
    hhi[i] = h;
    hlo[i] = __float2bfloat16(f - __bfloat162float(h));
}

// ---------------- fp32 GEMM 128x128x16, f32x2 (M0 only) ----------------------
__global__ __launch_bounds__(256, 2) void gemm_tn_128(
    const float* __restrict__ A, const float* __restrict__ B,
    const float* __restrict__ bias, float* __restrict__ C,
    int M, int N, int K)
{
    __shared__ float As[16 * 128];
    __shared__ float Bs[16 * 128];
    const int tid = threadIdx.x;
    const int m0 = blockIdx.y * 128;
    const int n0 = blockIdx.x * 128;
    const int ty = tid >> 4;
    const int tx = tid & 15;
    const int lr = tid >> 1;
    const int lk = (tid & 1) << 3;

    const float* Ap = A + (size_t)(m0 + lr) * K + lk;
    const float* Bp = B + (size_t)(n0 + lr) * K + lk;

    ull acc[8][4];
#pragma unroll
    for (int i = 0; i < 8; ++i)
#pragma unroll
        for (int j = 0; j < 4; ++j) acc[i][j] = 0ull;

    float4 pa0 = *(const float4*)Ap;
    float4 pa1 = *(const float4*)(Ap + 4);
    float4 pb0 = *(const float4*)Bp;
    float4 pb1 = *(const float4*)(Bp + 4);

    const int nch = K >> 4;
    for (int c = 0; c < nch; ++c) {
        As[(lk + 0) * 128 + lr] = pa0.x; As[(lk + 1) * 128 + lr] = pa0.y;
        As[(lk + 2) * 128 + lr] = pa0.z; As[(lk + 3) * 128 + lr] = pa0.w;
        As[(lk + 4) * 128 + lr] = pa1.x; As[(lk + 5) * 128 + lr] = pa1.y;
        As[(lk + 6) * 128 + lr] = pa1.z; As[(lk + 7) * 128 + lr] = pa1.w;
        Bs[(lk + 0) * 128 + lr] = pb0.x; Bs[(lk + 1) * 128 + lr] = pb0.y;
        Bs[(lk + 2) * 128 + lr] = pb0.z; Bs[(lk + 3) * 128 + lr] = pb0.w;
        Bs[(lk + 4) * 128 + lr] = pb1.x; Bs[(lk + 5) * 128 + lr] = pb1.y;
        Bs[(lk + 6) * 128 + lr] = pb1.z; Bs[(lk + 7) * 128 + lr] = pb1.w;
        __syncthreads();
        if (c + 1 < nch) {
            pa0 = *(const float4*)(Ap + (c + 1) * 16);
            pa1 = *(const float4*)(Ap + (c + 1) * 16 + 4);
            pb0 = *(const float4*)(Bp + (c + 1) * 16);
            pb1 = *(const float4*)(Bp + (c + 1) * 16 + 4);
        }
#pragma unroll
        for (int k = 0; k < 16; ++k) {
            float4 a0 = *(const float4*)&As[k * 128 + (ty << 2)];
            float4 a1 = *(const float4*)&As[k * 128 + (ty << 2) + 64];
            ulonglong2 b0 = *(const ulonglong2*)&Bs[k * 128 + (tx << 2)];
            ulonglong2 b1 = *(const ulonglong2*)&Bs[k * 128 + (tx << 2) + 64];
            ull ap[8];
            ap[0] = pack_rep(a0.x); ap[1] = pack_rep(a0.y);
            ap[2] = pack_rep(a0.z); ap[3] = pack_rep(a0.w);
            ap[4] = pack_rep(a1.x); ap[5] = pack_rep(a1.y);
            ap[6] = pack_rep(a1.z); ap[7] = pack_rep(a1.w);
#pragma unroll
            for (int i = 0; i < 8; ++i) {
                ffma2(acc[i][0], ap[i], b0.x);
                ffma2(acc[i][1], ap[i], b0.y);
                ffma2(acc[i][2], ap[i], b1.x);
                ffma2(acc[i][3], ap[i], b1.y);
            }
        }
        __syncthreads();
    }

    float bb[8];
#pragma unroll
    for (int j = 0; j < 4; ++j) {
        bb[j]     = bias[n0 + (tx << 2) + j];
        bb[4 + j] = bias[n0 + (tx << 2) + 64 + j];
    }
#pragma unroll
    for (int i = 0; i < 8; ++i) {
        int row = m0 + (ty << 2) + (i & 3) + ((i >> 2) << 6);
        float* Cp = C + (size_t)row * N + n0 + (tx << 2);
        float2 c0 = unpack2(acc[i][0]);
        float2 c1 = unpack2(acc[i][1]);
        float2 c2 = unpack2(acc[i][2]);
        float2 c3 = unpack2(acc[i][3]);
        float4 v0 = make_float4(c0.x + bb[0], c0.y + bb[1], c1.x + bb[2], c1.y + bb[3]);
        float4 v1 = make_float4(c2.x + bb[4], c2.y + bb[5], c3.x + bb[6], c3.y + bb[7]);
        *(float4*)Cp = v0;
        *(float4*)(Cp + 64) = v1;
    }
}

// ---------------- gx0 gather: gx0[bt, g] = M0T[X[bt], g] ---------------------
__global__ __launch_bounds__(256) void gx0_fill_kernel(const int* __restrict__ X)
{
    size_t idx = (size_t)blockIdx.x * 256 + threadIdx.x;
    int bt = (int)(idx / (G3 / 4));
    int gq = (int)(idx % (G3 / 4));
    int tok = X[bt];
    float4 v = ((const float4*)g_M0)[(size_t)tok * (G3 / 4) + gq];
    ((float4*)g_gx)[idx] = v;
}

// ---------------- bf16-split MMA GEMM: C[M,N] = Y @ B^T + bias ---------------
// A given as bf16 hi/lo arrays [M x 1024]; B fp32 [N x 1024] converted on the fly.
// Tile 128x64, 8 warps (warp tile 32x32). remapA: row r -> (r/511)*512 + r%511.
__global__ __launch_bounds__(256) void mma_gemm(
    const __nv_bfloat16* __restrict__ Ahi, const __nv_bfloat16* __restrict__ Alo,
    const float* __restrict__ B, const float* __restrict__ bias,
    float* __restrict__ C, int M, int N, int remapA)
{
    __shared__ __nv_bfloat16 sAhi[128 * 40], sAlo[128 * 40];
    __shared__ __nv_bfloat16 sBhi[64 * 40],  sBlo[64 * 40];
    const int tid = threadIdx.x, wid = tid >> 5, lane = tid & 31;
    const int m0 = blockIdx.y * 128, n0 = blockIdx.x * 64;
    const int wm = wid & 3, wn = wid >> 2;

    float acc[2][4][4];
#pragma unroll
    for (int mt = 0; mt < 2; ++mt)
#pragma unroll
        for (int nt = 0; nt < 4; ++nt)
#pragma unroll
            for (int q = 0; q < 4; ++q) acc[mt][nt][q] = 0.f;

    for (int c = 0; c < 32; ++c) {
        const int k0 = c * 32;
        // stage A (bf16 hi/lo, 128 rows x 32)
#pragma unroll
        for (int s = 0; s < 4; ++s) {
            int i = tid + s * 256;
            int arr = i >> 9, e = i & 511, row = e >> 2, q = e & 3;
            int r = m0 + row; if (r >= M) r = M - 1;
            if (remapA) r = (r / (Tsz - 1)) * Tsz + (r % (Tsz - 1));
            const __nv_bfloat16* src = arr ? Alo : Ahi;
            uint4 v = *(const uint4*)(src + (size_t)r * Hsz + k0 + q * 8);
            __nv_bfloat16* dst = (arr ? sAlo : sAhi) + row * 40 + q * 8;
            *(uint4*)dst = v;
        }
        // stage B (fp32 -> bf16 hi/lo, 64 rows x 32)
#pragma unroll
        for (int s = 0; s < 2; ++s) {
            int i = tid + s * 256;
            int row = i >> 3, q = i & 7;
            float4 v = *(const float4*)(B + (size_t)(n0 + row) * Hsz + k0 + q * 4);
            __nv_bfloat16 h0 = __float2bfloat16(v.x), h1 = __float2bfloat16(v.y);
            __nv_bfloat16 h2 = __float2bfloat16(v.z), h3 = __float2bfloat16(v.w);
            __nv_bfloat16 l0 = __float2bfloat16(v.x - __bfloat162float(h0));
            __nv_bfloat16 l1 = __float2bfloat16(v.y - __bfloat162float(h1));
            __nv_bfloat16 l2 = __float2bfloat16(v.z - __bfloat162float(h2));
            __nv_bfloat16 l3 = __float2bfloat16(v.w - __bfloat162float(h3));
            unsigned* dh = (unsigned*)(sBhi + row * 40 + q * 4);
            dh[0] = pack_bf16x2(h0, h1); dh[1] = pack_bf16x2(h2, h3);
            unsigned* dl = (unsigned*)(sBlo + row * 40 + q * 4);
            dl[0] = pack_bf16x2(l0, l1); dl[1] = pack_bf16x2(l2, l3);
        }
        __syncthreads();

        unsigned bh[4][4], bl[4][4];
#pragma unroll
        for (int nt = 0; nt < 4; ++nt) {
            const int brow = wn * 32 + nt * 8 + (lane & 7);
            ldsm4(bh[nt], sBhi + brow * 40 + ((lane >> 3) << 3));
            ldsm4(bl[nt], sBlo + brow * 40 + ((lane >> 3) << 3));
        }
#pragma unroll
        for (int kk = 0; kk < 2; ++kk) {
            unsigned ah[2][4], al[2][4];
#pragma unroll
            for (int mt = 0; mt < 2; ++mt) {
                const int aoff = (wm * 32 + mt * 16 + (lane & 15)) * 40 + kk * 16 + ((lane >> 4) << 3);
                ldsm4(ah[mt], sAhi + aoff);
                ldsm4(al[mt], sAlo + aoff);
            }
#pragma unroll
            for (int mt = 0; mt < 2; ++mt)
#pragma unroll
                for (int nt = 0; nt < 4; ++nt) {
                    mma_bf16(acc[mt][nt], ah[mt], bh[nt] + 2 * kk);
                    mma_bf16(acc[mt][nt], ah[mt], bl[nt] + 2 * kk);
                    mma_bf16(acc[mt][nt], al[mt], bh[nt] + 2 * kk);
                }
        }
        __syncthreads();
    }

    // epilogue
#pragma unroll
    for (int mt = 0; mt < 2; ++mt)
#pragma unroll
        for (int nt = 0; nt < 4; ++nt) {
            int r0 = m0 + wm * 32 + mt * 16 + (lane >> 2);
            int cb = n0 + wn * 32 + nt * 8 + 2 * (lane & 3);
            float b0 = bias[cb], b1 = bias[cb + 1];
            if (r0 < M) {
                C[(size_t)r0 * N + cb]     = acc[mt][nt][0] + b0;
                C[(size_t)r0 * N + cb + 1] = acc[mt][nt][1] + b1;
            }
            int r1 = r0 + 8;
            if (r1 < M) {
                C[(size_t)r1 * N + cb]     = acc[mt][nt][2] + b0;
                C[(size_t)r1 * N + cb + 1] = acc[mt][nt][3] + b1;
            }
        }
}

// ---------------- persistent GRU scan (bf16-split tensor cores) --------------
// 128 blocks x 384 threads (12 warps). Block owns 8 h-cols -> 24 gate-cols.
// Warp w: m-tile (w&3) of 16 batch rows, gate (w>>2). 3-term split MMA.
__global__ __launch_bounds__(384) void gru_scan_mma(
    const float* __restrict__ Whh, const float* __restrict__ bhh,
    const float* __restrict__ gx,
    __nv_bfloat16* __restrict__ yHi, __nv_bfloat16* __restrict__ yLo,
    float* __restrict__ hfA, float* __restrict__ hfB,
    __nv_bfloat16* __restrict__ hHiA, __nv_bfloat16* __restrict__ hHiB,
    __nv_bfloat16* __restrict__ hLoA, __nv_bfloat16* __restrict__ hLoB,
    int t_base)
{
    extern __shared__ __align__(16) unsigned char smraw[];
    __nv_bfloat16* sWhi = (__nv_bfloat16*)smraw;
    __nv_bfloat16* sWlo = sWhi + 24 * SWPAD;
    __nv_bfloat16* sHhi = sWlo + 24 * SWPAD;          // [2][64*SHPAD]
    __nv_bfloat16* sHlo = sHhi + 2 * 64 * SHPAD;
    float* ghs = (float*)(sHlo + 2 * 64 * SHPAD);     // [64][25]

    const int tid = threadIdx.x, wid = tid >> 5, lane = tid & 31;
    const int c0 = blockIdx.x << 3;
    const int mw = wid & 3, gt = wid >> 2;

    // Convert W strip to bf16 hi/lo in SMEM once per layer.
    for (int i = tid; i < 24 * 1024; i += 384) {
        int r = i >> 10, k = i & 1023;
        int g = r >> 3, jj = r & 7;
        float f = Whh[(size_t)(g * Hsz + c0 + jj) * Hsz + k];
        __nv_bfloat16 h = __float2bfloat16(f);
        sWhi[r * SWPAD + k] = h;
        sWlo[r * SWPAD + k] = __float2bfloat16(f - __bfloat162float(h));
    }
    float br = 0.f, bz = 0.f, bn = 0.f;
    if (tid < 256) {
        int j = c0 + (tid & 7);
        br = bhh[j]; bz = bhh[Hsz + j]; bn = bhh[2 * Hsz + j];
    }
    __syncthreads();

    for (int t = 0; t < Tsz; ++t) {
        const int par = t & 1;
        const float* hfIn  = par ? hfB : hfA;
        float*       hfOut = par ? hfA : hfB;
        const __nv_bfloat16* hHiIn = par ? hHiB : hHiA;
        const __nv_bfloat16* hLoIn = par ? hLoB : hLoA;
        __nv_bfloat16* hHiOut = par ? hHiA : hHiB;
        __nv_bfloat16* hLoOut = par ? hLoA : hLoB;

        uint4 stg[6];
        // stage chunk 0
#pragma unroll
        for (int s = 0; s < 6; ++s) {
            int i = tid + s * 384;
            if (i < 2048) {
                int arr = i >> 10, e = i & 1023, row = e >> 4, q = e & 15;
                const __nv_bfloat16* src = arr ? hLoIn : hHiIn;
                stg[s] = __ldcg((const uint4*)(src + (size_t)row * Hsz) + q);
            }
        }
#pragma unroll
        for (int s = 0; s < 6; ++s) {
            int i = tid + s * 384;
            if (i < 2048) {
                int arr = i >> 10, e = i & 1023, row = e >> 4, q = e & 15;
                __nv_bfloat16* dst = (arr ? sHlo : sHhi) + row * SHPAD + q * 8;
                *(uint4*)dst = stg[s];
            }
        }
        __syncthreads();

        float acc[4] = {0.f, 0.f, 0.f, 0.f};
        for (int c = 0; c < 8; ++c) {
            if (c < 7) {
#pragma unroll
                for (int s = 0; s < 6; ++s) {
                    int i = tid + s * 384;
                    if (i < 2048) {
                        int arr = i >> 10, e = i & 1023, row = e >> 4, q = e & 15;
                        const __nv_bfloat16* src = arr ? hLoIn : hHiIn;
                        stg[s] = __ldcg((const uint4*)(src + (size_t)row * Hsz + (c + 1) * 128) + q);
                    }
                }
            }
            const __nv_bfloat16* Hh = sHhi + (c & 1) * 64 * SHPAD;
            const __nv_bfloat16* Hl = sHlo + (c & 1) * 64 * SHPAD;
#pragma unroll
            for (int kt = 0; kt < 4; ++kt) {
                unsigned bh[4], bl[4];
                const int woff = (gt * 8 + (lane & 7)) * SWPAD + c * 128 + kt * 32 + ((lane >> 3) << 3);
                ldsm4(bh, sWhi + woff);
                ldsm4(bl, sWlo + woff);
#pragma unroll
                for (int kk = 0; kk < 2; ++kk) {
                    unsigned ah[4], al[4];
                    const int aoff = (mw * 16 + (lane & 15)) * SHPAD + kt * 32 + kk * 16 + ((lane >> 4) << 3);
                    ldsm4(ah, Hh + aoff);
                    ldsm4(al, Hl + aoff);
                    mma_bf16(acc, ah, bh + 2 * kk);
                    mma_bf16(acc, ah, bl + 2 * kk);
                    mma_bf16(acc, al, bh + 2 * kk);
                }
            }
            if (c < 7) {
#pragma unroll
                for (int s = 0; s < 6; ++s) {
                    int i = tid + s * 384;
                    if (i < 2048) {
                        int arr = i >> 10, e = i & 1023, row = e >> 4, q = e & 15;
                        __nv_bfloat16* dst = (arr ? sHlo : sHhi) + ((c + 1) & 1) * 64 * SHPAD + row * SHPAD + q * 8;
                        *(uint4*)dst = stg[s];
                    }
                }
                __syncthreads();
            }
        }

        // write gh preacts to SMEM
        {
            int row = mw * 16 + (lane >> 2);
            int gcol = gt * 8 + 2 * (lane & 3);
            ghs[row * 25 + gcol]           = acc[0];
            ghs[row * 25 + gcol + 1]       = acc[1];
            ghs[(row + 8) * 25 + gcol]     = acc[2];
            ghs[(row + 8) * 25 + gcol + 1] = acc[3];
        }
        __syncthreads();

        // gates + state update (threads 0..255)
        if (tid < 256) {
            const int ty = tid >> 3, tx = tid & 7;
            const int j = c0 + tx;
#pragma unroll
            for (int r = 0; r < 2; ++r) {
                const int b = ty + (r << 5);
                const float a0 = ghs[b * 25 + tx];
                const float a1 = ghs[b * 25 + 8 + tx];
                const float a2 = ghs[b * 25 + 16 + tx];
                const size_t rowbt = (size_t)b * Tsz + t;
                const float* gxr = gx + rowbt * G3;
                const float xr = gxr[j];
                const float xz = gxr[Hsz + j];
                const float xn = gxr[2 * Hsz + j];
                const float rg = 1.0f / (1.0f + expf(-(xr + a0 + br)));
                const float zg = 1.0f / (1.0f + expf(-(xz + a1 + bz)));
                const float ng = tanhf(xn + rg * (a2 + bn));
                const float hold = hfIn[(size_t)b * Hsz + j];
                const float hnew = (1.0f - zg) * ng + zg * hold;
                hfOut[(size_t)b * Hsz + j] = hnew;
                __nv_bfloat16 hh = __float2bfloat16(hnew);
                __nv_bfloat16 hl = __float2bfloat16(hnew - __bfloat162float(hh));
                hHiOut[(size_t)b * Hsz + j] = hh;
                hLoOut[(size_t)b * Hsz + j] = hl;
                yHi[rowbt * Hsz + j] = hh;
                yLo[rowbt * Hsz + j] = hl;
            }
        }

        // ---- grid barrier ----
        __syncthreads();
        if (tid == 0) {
            __threadfence();
            atomicAdd(&g_bar, 1u);
            const unsigned target = (unsigned)NBLK * (unsigned)(t_base + t + 1);
            unsigned v;
            do {
                asm volatile("ld.global.acquire.gpu.u32 %0, [%1];"
                             : "=r"(v) : "l"(&g_bar));
            } while (v < target);
        }
        __syncthreads();
    }
}

// ---------------- launch ------------------------------------------------------
extern "C" void kernel_launch(void* const* d_in, const int* in_sizes, int n_in,
                              void* d_out, int out_size)
{
    const int*   X     = (const int*)d_in[0];
    const float* h0    = (const float*)d_in[1];
    const float* emb   = (const float*)d_in[2];
    const float* W_ih  = (const float*)d_in[3];
    const float* W_hh  = (const float*)d_in[4];
    const float* b_ih  = (const float*)d_in[5];
    const float* b_hh  = (const float*)d_in[6];
    const float* W_out = (const float*)d_in[7];
    const float* b_out = (const float*)d_in[8];
    float* out = (float*)d_out;

    float *pM0, *pgx, *phFA, *phFB;
    __nv_bfloat16 *pyHi, *pyLo, *phHiA, *phHiB, *phLoA, *phLoB;
    cudaGetSymbolAddress((void**)&pM0,  g_M0);
    cudaGetSymbolAddress((void**)&pgx,  g_gx);
    cudaGetSymbolAddress((void**)&pyHi, g_yHi);
    cudaGetSymbolAddress((void**)&pyLo, g_yLo);
    cudaGetSymbolAddress((void**)&phFA, g_hFA);
    cudaGetSymbolAddress((void**)&phFB, g_hFB);
    cudaGetSymbolAddress((void**)&phHiA, g_hHiA);
    cudaGetSymbolAddress((void**)&phHiB, g_hHiB);
    cudaGetSymbolAddress((void**)&phLoA, g_hLoA);
    cudaGetSymbolAddress((void**)&phLoB, g_hLoB);

    cudaFuncSetAttribute(gru_scan_mma,
                         cudaFuncAttributeMaxDynamicSharedMemorySize, SCAN_SMEM_B);

    // 0) reset grid barrier
    zero_bar_kernel<<<1, 1>>>();

    // 1) M0T[v,g] = emb[v].W_ih0[g] + b_ih0[g]
    {
        dim3 grid(G3 / 128, Vsz / 128);
        gemm_tn_128<<<grid, 256>>>(emb, W_ih, b_ih, pM0, Vsz, G3, Hsz);
    }

    // 2) gx0 gather
    gx0_fill_kernel<<<(Bsz * Tsz * (G3 / 4)) / 256, 256>>>(X);

    // 3) layer-0 scan
    hinit_kernel<<<Bsz * Hsz / 256, 256>>>(h0, phFA, phHiA, phLoA);
    gru_scan_mma<<<NBLK, 384, SCAN_SMEM_B>>>(W_hh, b_hh, pgx, pyHi, pyLo,
                                             phFA, phFB, phHiA, phHiB, phLoA, phLoB, 0);

    // 4) gx1 = y0 @ W_ih1^T + b_ih1  (bf16-split MMA)
    {
        dim3 grid(G3 / 64, (Bsz * Tsz) / 128);
        mma_gemm<<<grid, 256>>>(pyHi, pyLo, W_ih + (size_t)G3 * Hsz, b_ih + G3,
                                pgx, Bsz * Tsz, G3, 0);
    }

    // 5) layer-1 scan (barrier counter continues)
    hinit_kernel<<<Bsz * Hsz / 256, 256>>>(h0 + Bsz * Hsz, phFA, phHiA, phLoA);
    gru_scan_mma<<<NBLK, 384, SCAN_SMEM_B>>>(W_hh + (size_t)G3 * Hsz, b_hh + G3,
                                             pgx, pyHi, pyLo,
                                             phFA, phFB, phHiA, phHiB, phLoA, phLoB, Tsz);

    // 6) logits for t < T-1 (bf16-split MMA, row remap skips last timestep)
    {
        int M = Bsz * (Tsz - 1);                 // 32704
        dim3 grid(Vsz / 64, (M + 127) / 128);
        mma_gemm<<<grid, 256>>>(pyHi, pyLo, W_out, b_out, out, M, Vsz, 1);
    }
}

// round 8
// speedup vs baseline: 3.2907x; 1.0731x over previous
#include <cuda_runtime.h>
#include <cuda_bf16.h>
#include <math.h>

// Problem constants
#define Bsz 64
#define Tsz 512
#define Vsz 256
#define Hsz 1024
#define G3  3072   // 3*H
#define NBLK 128

#define SWPAD 1032       // W strip row stride (bf16) -> ldmatrix conflict-free
#define SHPAD 136        // h chunk row stride (bf16)
#define SCAN_SMEM_B ((24*SWPAD*2 + 2*64*SHPAD*2)*2 + 64*25*4)   // 175104 B

typedef unsigned long long ull;

// ---------------- mma.sync helpers ------------------------------------------
__device__ __forceinline__ void mma_bf16(float* c, const unsigned* a, const unsigned* b) {
    asm volatile(
        "mma.sync.aligned.m16n8k16.row.col.f32.bf16.bf16.f32 "
        "{%0,%1,%2,%3}, {%4,%5,%6,%7}, {%8,%9}, {%0,%1,%2,%3};\n"
        : "+f"(c[0]), "+f"(c[1]), "+f"(c[2]), "+f"(c[3])
        : "r"(a[0]), "r"(a[1]), "r"(a[2]), "r"(a[3]), "r"(b[0]), "r"(b[1]));
}
__device__ __forceinline__ void ldsm4(unsigned* r, const void* p) {
    unsigned a = (unsigned)__cvta_generic_to_shared(p);
    asm volatile("ldmatrix.sync.aligned.m8n8.x4.shared.b16 {%0,%1,%2,%3}, [%4];"
                 : "=r"(r[0]), "=r"(r[1]), "=r"(r[2]), "=r"(r[3]) : "r"(a));
}
__device__ __forceinline__ unsigned pack_bf16x2(__nv_bfloat16 a, __nv_bfloat16 b) {
    __nv_bfloat162 t; t.x = a; t.y = b;
    return *(unsigned*)&t;
}

// packed fp32x2 FMA (kept for the fp32 M0 GEMM)
__device__ __forceinline__ void ffma2(ull& d, ull a, ull b) {
    asm("fma.rn.f32x2 %0, %1, %2, %0;" : "+l"(d) : "l"(a), "l"(b));
}
__device__ __forceinline__ ull pack_rep(float v) {
    ull r; unsigned u = __float_as_uint(v);
    asm("mov.b64 %0, {%1, %1};" : "=l"(r) : "r"(u));
    return r;
}
__device__ __forceinline__ float2 unpack2(ull v) {
    float2 r;
    asm("mov.b64 {%0, %1}, %2;" : "=f"(r.x), "=f"(r.y) : "l"(v));
    return r;
}

// ---------------- scratch (static __device__, no allocations) ----------------
__device__ float g_M0[(size_t)Vsz * G3];
__device__ float g_gx[(size_t)Bsz * Tsz * G3];
__device__ __nv_bfloat16 g_yHi[(size_t)Bsz * Tsz * Hsz];
__device__ __nv_bfloat16 g_yLo[(size_t)Bsz * Tsz * Hsz];
__device__ float g_hFA[Bsz * Hsz];
__device__ float g_hFB[Bsz * Hsz];
__device__ __nv_bfloat16 g_hHiA[Bsz * Hsz], g_hHiB[Bsz * Hsz];
__device__ __nv_bfloat16 g_hLoA[Bsz * Hsz], g_hLoB[Bsz * Hsz];
__device__ unsigned g_bar;

// ---------------- h0 init: fp32 copy + bf16 hi/lo split ----------------------
__global__ __launch_bounds__(256) void hinit_kernel(
    const float* __restrict__ src, float* __restrict__ hf,
    __nv_bfloat16* __restrict__ hhi, __nv_bfloat16* __restrict__ hlo)
{
    int i = blockIdx.x * 256 + threadIdx.x;
    float f = src[i];
    hf[i] = f;
    __nv_bfloat16 h = __float2bfloat16(f);
    hhi[i] = h;
    hlo[i] = __float2bfloat16(f - __bfloat162float(h));
}

// ---------------- fp32 GEMM 128x128x16, f32x2 (M0 only; also zeroes g_bar) ---
__global__ __launch_bounds__(256, 2) void gemm_tn_128(
    const float* __restrict__ A, const float* __restrict__ B,
    const float* __restrict__ bias, float* __restrict__ C,
    int M, int N, int K)
{
    if (blockIdx.x == 0 && blockIdx.y == 0 && threadIdx.x == 0) g_bar = 0u;

    __shared__ float As[16 * 128];
    __shared__ float Bs[16 * 128];
    const int tid = threadIdx.x;
    const int m0 = blockIdx.y * 128;
    const int n0 = blockIdx.x * 128;
    const int ty = tid >> 4;
    const int tx = tid & 15;
    const int lr = tid >> 1;
    const int lk = (tid & 1) << 3;

    const float* Ap = A + (size_t)(m0 + lr) * K + lk;
    const float* Bp = B + (size_t)(n0 + lr) * K + lk;

    ull acc[8][4];
#pragma unroll
    for (int i = 0; i < 8; ++i)
#pragma unroll
        for (int j = 0; j < 4; ++j) acc[i][j] = 0ull;

    float4 pa0 = *(const float4*)Ap;
    float4 pa1 = *(const float4*)(Ap + 4);
    float4 pb0 = *(const float4*)Bp;
    float4 pb1 = *(const float4*)(Bp + 4);

    const int nch = K >> 4;
    for (int c = 0; c < nch; ++c) {
        As[(lk + 0) * 128 + lr] = pa0.x; As[(lk + 1) * 128 + lr] = pa0.y;
        As[(lk + 2) * 128 + lr] = pa0.z; As[(lk + 3) * 128 + lr] = pa0.w;
        As[(lk + 4) * 128 + lr] = pa1.x; As[(lk + 5) * 128 + lr] = pa1.y;
        As[(lk + 6) * 128 + lr] = pa1.z; As[(lk + 7) * 128 + lr] = pa1.w;
        Bs[(lk + 0) * 128 + lr] = pb0.x; Bs[(lk + 1) * 128 + lr] = pb0.y;
        Bs[(lk + 2) * 128 + lr] = pb0.z; Bs[(lk + 3) * 128 + lr] = pb0.w;
        Bs[(lk + 4) * 128 + lr] = pb1.x; Bs[(lk + 5) * 128 + lr] = pb1.y;
        Bs[(lk + 6) * 128 + lr] = pb1.z; Bs[(lk + 7) * 128 + lr] = pb1.w;
        __syncthreads();
        if (c + 1 < nch) {
            pa0 = *(const float4*)(Ap + (c + 1) * 16);
            pa1 = *(const float4*)(Ap + (c + 1) * 16 + 4);
            pb0 = *(const float4*)(Bp + (c + 1) * 16);
            pb1 = *(const float4*)(Bp + (c + 1) * 16 + 4);
        }
#pragma unroll
        for (int k = 0; k < 16; ++k) {
            float4 a0 = *(const float4*)&As[k * 128 + (ty << 2)];
            float4 a1 = *(const float4*)&As[k * 128 + (ty << 2) + 64];
            ulonglong2 b0 = *(const ulonglong2*)&Bs[k * 128 + (tx << 2)];
            ulonglong2 b1 = *(const ulonglong2*)&Bs[k * 128 + (tx << 2) + 64];
            ull ap[8];
            ap[0] = pack_rep(a0.x); ap[1] = pack_rep(a0.y);
            ap[2] = pack_rep(a0.z); ap[3] = pack_rep(a0.w);
            ap[4] = pack_rep(a1.x); ap[5] = pack_rep(a1.y);
            ap[6] = pack_rep(a1.z); ap[7] = pack_rep(a1.w);
#pragma unroll
            for (int i = 0; i < 8; ++i) {
                ffma2(acc[i][0], ap[i], b0.x);
                ffma2(acc[i][1], ap[i], b0.y);
                ffma2(acc[i][2], ap[i], b1.x);
                ffma2(acc[i][3], ap[i], b1.y);
            }
        }
        __syncthreads();
    }

    float bb[8];
#pragma unroll
    for (int j = 0; j < 4; ++j) {
        bb[j]     = bias[n0 + (tx << 2) + j];
        bb[4 + j] = bias[n0 + (tx << 2) + 64 + j];
    }
#pragma unroll
    for (int i = 0; i < 8; ++i) {
        int row = m0 + (ty << 2) + (i & 3) + ((i >> 2) << 6);
        float* Cp = C + (size_t)row * N + n0 + (tx << 2);
        float2 c0 = unpack2(acc[i][0]);
        float2 c1 = unpack2(acc[i][1]);
        float2 c2 = unpack2(acc[i][2]);
        float2 c3 = unpack2(acc[i][3]);
        float4 v0 = make_float4(c0.x + bb[0], c0.y + bb[1], c1.x + bb[2], c1.y + bb[3]);
        float4 v1 = make_float4(c2.x + bb[4], c2.y + bb[5], c3.x + bb[6], c3.y + bb[7]);
        *(float4*)Cp = v0;
        *(float4*)(Cp + 64) = v1;
    }
}

// ---------------- gx0 gather: gx0[bt, g] = M0T[X[bt], g] ---------------------
__global__ __launch_bounds__(256) void gx0_fill_kernel(const int* __restrict__ X)
{
    size_t idx = (size_t)blockIdx.x * 256 + threadIdx.x;
    int bt = (int)(idx / (G3 / 4));
    int gq = (int)(idx % (G3 / 4));
    int tok = X[bt];
    float4 v = ((const float4*)g_M0)[(size_t)tok * (G3 / 4) + gq];
    ((float4*)g_gx)[idx] = v;
}

// ---------------- bf16-split MMA GEMM: C[M,N] = Y @ B^T + bias ---------------
__global__ __launch_bounds__(256) void mma_gemm(
    const __nv_bfloat16* __restrict__ Ahi, const __nv_bfloat16* __restrict__ Alo,
    const float* __restrict__ B, const float* __restrict__ bias,
    float* __restrict__ C, int M, int N, int remapA)
{
    __shared__ __nv_bfloat16 sAhi[128 * 40], sAlo[128 * 40];
    __shared__ __nv_bfloat16 sBhi[64 * 40],  sBlo[64 * 40];
    const int tid = threadIdx.x, wid = tid >> 5, lane = tid & 31;
    const int m0 = blockIdx.y * 128, n0 = blockIdx.x * 64;
    const int wm = wid & 3, wn = wid >> 2;

    float acc[2][4][4];
#pragma unroll
    for (int mt = 0; mt < 2; ++mt)
#pragma unroll
        for (int nt = 0; nt < 4; ++nt)
#pragma unroll
            for (int q = 0; q < 4; ++q) acc[mt][nt][q] = 0.f;

    for (int c = 0; c < 32; ++c) {
        const int k0 = c * 32;
#pragma unroll
        for (int s = 0; s < 4; ++s) {
            int i = tid + s * 256;
            int arr = i >> 9, e = i & 511, row = e >> 2, q = e & 3;
            int r = m0 + row; if (r >= M) r = M - 1;
            if (remapA) r = (r / (Tsz - 1)) * Tsz + (r % (Tsz - 1));
            const __nv_bfloat16* src = arr ? Alo : Ahi;
            uint4 v = *(const uint4*)(src + (size_t)r * Hsz + k0 + q * 8);
            __nv_bfloat16* dst = (arr ? sAlo : sAhi) + row * 40 + q * 8;
            *(uint4*)dst = v;
        }
#pragma unroll
        for (int s = 0; s < 2; ++s) {
            int i = tid + s * 256;
            int row = i >> 3, q = i & 7;
            float4 v = *(const float4*)(B + (size_t)(n0 + row) * Hsz + k0 + q * 4);
            __nv_bfloat16 h0 = __float2bfloat16(v.x), h1 = __float2bfloat16(v.y);
            __nv_bfloat16 h2 = __float2bfloat16(v.z), h3 = __float2bfloat16(v.w);
            __nv_bfloat16 l0 = __float2bfloat16(v.x - __bfloat162float(h0));
            __nv_bfloat16 l1 = __float2bfloat16(v.y - __bfloat162float(h1));
            __nv_bfloat16 l2 = __float2bfloat16(v.z - __bfloat162float(h2));
            __nv_bfloat16 l3 = __float2bfloat16(v.w - __bfloat162float(h3));
            unsigned* dh = (unsigned*)(sBhi + row * 40 + q * 4);
            dh[0] = pack_bf16x2(h0, h1); dh[1] = pack_bf16x2(h2, h3);
            unsigned* dl = (unsigned*)(sBlo + row * 40 + q * 4);
            dl[0] = pack_bf16x2(l0, l1); dl[1] = pack_bf16x2(l2, l3);
        }
        __syncthreads();

        unsigned bh[4][4], bl[4][4];
#pragma unroll
        for (int nt = 0; nt < 4; ++nt) {
            const int brow = wn * 32 + nt * 8 + (lane & 7);
            ldsm4(bh[nt], sBhi + brow * 40 + ((lane >> 3) << 3));
            ldsm4(bl[nt], sBlo + brow * 40 + ((lane >> 3) << 3));
        }
#pragma unroll
        for (int kk = 0; kk < 2; ++kk) {
            unsigned ah[2][4], al[2][4];
#pragma unroll
            for (int mt = 0; mt < 2; ++mt) {
                const int aoff = (wm * 32 + mt * 16 + (lane & 15)) * 40 + kk * 16 + ((lane >> 4) << 3);
                ldsm4(ah[mt], sAhi + aoff);
                ldsm4(al[mt], sAlo + aoff);
            }
#pragma unroll
            for (int mt = 0; mt < 2; ++mt)
#pragma unroll
                for (int nt = 0; nt < 4; ++nt) {
                    mma_bf16(acc[mt][nt], ah[mt], bh[nt] + 2 * kk);
                    mma_bf16(acc[mt][nt], ah[mt], bl[nt] + 2 * kk);
                    mma_bf16(acc[mt][nt], al[mt], bh[nt] + 2 * kk);
                }
        }
        __syncthreads();
    }

#pragma unroll
    for (int mt = 0; mt < 2; ++mt)
#pragma unroll
        for (int nt = 0; nt < 4; ++nt) {
            int r0 = m0 + wm * 32 + mt * 16 + (lane >> 2);
            int cb = n0 + wn * 32 + nt * 8 + 2 * (lane & 3);
            float b0 = bias[cb], b1 = bias[cb + 1];
            if (r0 < M) {
                C[(size_t)r0 * N + cb]     = acc[mt][nt][0] + b0;
                C[(size_t)r0 * N + cb + 1] = acc[mt][nt][1] + b1;
            }
            int r1 = r0 + 8;
            if (r1 < M) {
                C[(size_t)r1 * N + cb]     = acc[mt][nt][2] + b0;
                C[(size_t)r1 * N + cb + 1] = acc[mt][nt][3] + b1;
            }
        }
}

// ---------------- persistent GRU scan (bf16-split tensor cores) --------------
// 3 independent accumulator groups break the MMA RAW chain; gx prefetched.
__global__ __launch_bounds__(384) void gru_scan_mma(
    const float* __restrict__ Whh, const float* __restrict__ bhh,
    const float* __restrict__ gx,
    __nv_bfloat16* __restrict__ yHi, __nv_bfloat16* __restrict__ yLo,
    float* __restrict__ hfA, float* __restrict__ hfB,
    __nv_bfloat16* __restrict__ hHiA, __nv_bfloat16* __restrict__ hHiB,
    __nv_bfloat16* __restrict__ hLoA, __nv_bfloat16* __restrict__ hLoB,
    int t_base)
{
    extern __shared__ __align__(16) unsigned char smraw[];
    __nv_bfloat16* sWhi = (__nv_bfloat16*)smraw;
    __nv_bfloat16* sWlo = sWhi + 24 * SWPAD;
    __nv_bfloat16* sHhi = sWlo + 24 * SWPAD;          // [2][64*SHPAD]
    __nv_bfloat16* sHlo = sHhi + 2 * 64 * SHPAD;
    float* ghs = (float*)(sHlo + 2 * 64 * SHPAD);     // [64][25]

    const int tid = threadIdx.x, wid = tid >> 5, lane = tid & 31;
    const int c0 = blockIdx.x << 3;
    const int mw = wid & 3, gt = wid >> 2;

    // Convert W strip to bf16 hi/lo in SMEM once per layer.
    for (int i = tid; i < 24 * 1024; i += 384) {
        int r = i >> 10, k = i & 1023;
        int g = r >> 3, jj = r & 7;
        float f = Whh[(size_t)(g * Hsz + c0 + jj) * Hsz + k];
        __nv_bfloat16 h = __float2bfloat16(f);
        sWhi[r * SWPAD + k] = h;
        sWlo[r * SWPAD + k] = __float2bfloat16(f - __bfloat162float(h));
    }
    float br = 0.f, bz = 0.f, bn = 0.f;
    const int gy = tid >> 3, gxc = tid & 7;
    const int jcol = c0 + gxc;
    if (tid < 256) {
        br = bhh[jcol]; bz = bhh[Hsz + jcol]; bn = bhh[2 * Hsz + jcol];
    }
    __syncthreads();

    for (int t = 0; t < Tsz; ++t) {
        const int par = t & 1;
        const float* hfIn  = par ? hfB : hfA;
        float*       hfOut = par ? hfA : hfB;
        const __nv_bfloat16* hHiIn = par ? hHiB : hHiA;
        const __nv_bfloat16* hLoIn = par ? hLoB : hLoA;
        __nv_bfloat16* hHiOut = par ? hHiA : hHiB;
        __nv_bfloat16* hLoOut = par ? hLoA : hLoB;

        uint4 stg[6];
        // issue chunk-0 staging loads
#pragma unroll
        for (int s = 0; s < 6; ++s) {
            int i = tid + s * 384;
            if (i < 2048) {
                int arr = i >> 10, e = i & 1023, row = e >> 4, q = e & 15;
                const __nv_bfloat16* src = arr ? hLoIn : hHiIn;
                stg[s] = __ldcg((const uint4*)(src + (size_t)row * Hsz) + q);
            }
        }
        // prefetch gate preacts (consumed at the end of the step)
        float pxr[2], pxz[2], pxn[2], phold[2];
        if (tid < 256) {
#pragma unroll
            for (int r = 0; r < 2; ++r) {
                const int b = gy + (r << 5);
                const float* gxr = gx + ((size_t)b * Tsz + t) * G3;
                pxr[r] = __ldcg(gxr + jcol);
                pxz[r] = __ldcg(gxr + Hsz + jcol);
                pxn[r] = __ldcg(gxr + 2 * Hsz + jcol);
                phold[r] = hfIn[(size_t)b * Hsz + jcol];
            }
        }
#pragma unroll
        for (int s = 0; s < 6; ++s) {
            int i = tid + s * 384;
            if (i < 2048) {
                int arr = i >> 10, e = i & 1023, row = e >> 4, q = e & 15;
                __nv_bfloat16* dst = (arr ? sHlo : sHhi) + row * SHPAD + q * 8;
                *(uint4*)dst = stg[s];
            }
        }
        __syncthreads();

        float aA[4] = {0.f, 0.f, 0.f, 0.f};
        float aB[4] = {0.f, 0.f, 0.f, 0.f};
        float aC[4] = {0.f, 0.f, 0.f, 0.f};
        for (int c = 0; c < 8; ++c) {
            if (c < 7) {
#pragma unroll
                for (int s = 0; s < 6; ++s) {
                    int i = tid + s * 384;
                    if (i < 2048) {
                        int arr = i >> 10, e = i & 1023, row = e >> 4, q = e & 15;
                        const __nv_bfloat16* src = arr ? hLoIn : hHiIn;
                        stg[s] = __ldcg((const uint4*)(src + (size_t)row * Hsz + (c + 1) * 128) + q);
                    }
                }
            }
            const __nv_bfloat16* Hh = sHhi + (c & 1) * 64 * SHPAD;
            const __nv_bfloat16* Hl = sHlo + (c & 1) * 64 * SHPAD;
#pragma unroll
            for (int kt = 0; kt < 4; ++kt) {
                unsigned bh[4], bl[4];
                const int woff = (gt * 8 + (lane & 7)) * SWPAD + c * 128 + kt * 32 + ((lane >> 3) << 3);
                ldsm4(bh, sWhi + woff);
                ldsm4(bl, sWlo + woff);
#pragma unroll
                for (int kk = 0; kk < 2; ++kk) {
                    unsigned ah[4], al[4];
                    const int aoff = (mw * 16 + (lane & 15)) * SHPAD + kt * 32 + kk * 16 + ((lane >> 4) << 3);
                    ldsm4(ah, Hh + aoff);
                    ldsm4(al, Hl + aoff);
                    mma_bf16(aA, ah, bh + 2 * kk);
                    mma_bf16(aB, ah, bl + 2 * kk);
                    mma_bf16(aC, al, bh + 2 * kk);
                }
            }
            if (c < 7) {
#pragma unroll
                for (int s = 0; s < 6; ++s) {
                    int i = tid + s * 384;
                    if (i < 2048) {
                        int arr = i >> 10, e = i & 1023, row = e >> 4, q = e & 15;
                        __nv_bfloat16* dst = (arr ? sHlo : sHhi) + ((c + 1) & 1) * 64 * SHPAD + row * SHPAD + q * 8;
                        *(uint4*)dst = stg[s];
                    }
                }
                __syncthreads();
            }
        }

        // write gh preacts to SMEM
        {
            int row = mw * 16 + (lane >> 2);
            int gcol = gt * 8 + 2 * (lane & 3);
            ghs[row * 25 + gcol]           = aA[0] + aB[0] + aC[0];
            ghs[row * 25 + gcol + 1]       = aA[1] + aB[1] + aC[1];
            ghs[(row + 8) * 25 + gcol]     = aA[2] + aB[2] + aC[2];
            ghs[(row + 8) * 25 + gcol + 1] = aA[3] + aB[3] + aC[3];
        }
        __syncthreads();

        // gates + state update (threads 0..255)
        if (tid < 256) {
#pragma unroll
            for (int r = 0; r < 2; ++r) {
                const int b = gy + (r << 5);
                const float a0 = ghs[b * 25 + gxc];
                const float a1 = ghs[b * 25 + 8 + gxc];
                const float a2 = ghs[b * 25 + 16 + gxc];
                const size_t rowbt = (size_t)b * Tsz + t;
                const float rg = 1.0f / (1.0f + expf(-(pxr[r] + a0 + br)));
                const float zg = 1.0f / (1.0f + expf(-(pxz[r] + a1 + bz)));
                const float ng = tanhf(pxn[r] + rg * (a2 + bn));
                const float hnew = (1.0f - zg) * ng + zg * phold[r];
                hfOut[(size_t)b * Hsz + jcol] = hnew;
                __nv_bfloat16 hh = __float2bfloat16(hnew);
                __nv_bfloat16 hl = __float2bfloat16(hnew - __bfloat162float(hh));
                hHiOut[(size_t)b * Hsz + jcol] = hh;
                hLoOut[(size_t)b * Hsz + jcol] = hl;
                yHi[rowbt * Hsz + jcol] = hh;
                yLo[rowbt * Hsz + jcol] = hl;
            }
        }

        // ---- grid barrier ----
        __syncthreads();
        if (tid == 0) {
            __threadfence();
            atomicAdd(&g_bar, 1u);
            const unsigned target = (unsigned)NBLK * (unsigned)(t_base + t + 1);
            unsigned v;
            do {
                asm volatile("ld.global.acquire.gpu.u32 %0, [%1];"
                             : "=r"(v) : "l"(&g_bar));
            } while (v < target);
        }
        __syncthreads();
    }
}

// ---------------- launch ------------------------------------------------------
extern "C" void kernel_launch(void* const* d_in, const int* in_sizes, int n_in,
                              void* d_out, int out_size)
{
    const int*   X     = (const int*)d_in[0];
    const float* h0    = (const float*)d_in[1];
    const float* emb   = (const float*)d_in[2];
    const float* W_ih  = (const float*)d_in[3];
    const float* W_hh  = (const float*)d_in[4];
    const float* b_ih  = (const float*)d_in[5];
    const float* b_hh  = (const float*)d_in[6];
    const float* W_out = (const float*)d_in[7];
    const float* b_out = (const float*)d_in[8];
    float* out = (float*)d_out;

    float *pM0, *pgx, *phFA, *phFB;
    __nv_bfloat16 *pyHi, *pyLo, *phHiA, *phHiB, *phLoA, *phLoB;
    cudaGetSymbolAddress((void**)&pM0,  g_M0);
    cudaGetSymbolAddress((void**)&pgx,  g_gx);
    cudaGetSymbolAddress((void**)&pyHi, g_yHi);
    cudaGetSymbolAddress((void**)&pyLo, g_yLo);
    cudaGetSymbolAddress((void**)&phFA, g_hFA);
    cudaGetSymbolAddress((void**)&phFB, g_hFB);
    cudaGetSymbolAddress((void**)&phHiA, g_hHiA);
    cudaGetSymbolAddress((void**)&phHiB, g_hHiB);
    cudaGetSymbolAddress((void**)&phLoA, g_hLoA);
    cudaGetSymbolAddress((void**)&phLoB, g_hLoB);

    cudaFuncSetAttribute(gru_scan_mma,
                         cudaFuncAttributeMaxDynamicSharedMemorySize, SCAN_SMEM_B);

    // 1) h0 split for layer 0
    hinit_kernel<<<Bsz * Hsz / 256, 256>>>(h0, phFA, phHiA, phLoA);

    // 2) M0T[v,g] = emb[v].W_ih0[g] + b_ih0[g]  (also zeroes grid barrier)
    {
        dim3 grid(G3 / 128, Vsz / 128);
        gemm_tn_128<<<grid, 256>>>(emb, W_ih, b_ih, pM0, Vsz, G3, Hsz);
    }

    // 3) gx0 gather
    gx0_fill_kernel<<<(Bsz * Tsz * (G3 / 4)) / 256, 256>>>(X);

    // 4) layer-0 scan  (4th launch -> ncu capture slot)
    gru_scan_mma<<<NBLK, 384, SCAN_SMEM_B>>>(W_hh, b_hh, pgx, pyHi, pyLo,
                                             phFA, phFB, phHiA, phHiB, phLoA, phLoB, 0);

    // 5) gx1 = y0 @ W_ih1^T + b_ih1
    {
        dim3 grid(G3 / 64, (Bsz * Tsz) / 128);
        mma_gemm<<<grid, 256>>>(pyHi, pyLo, W_ih + (size_t)G3 * Hsz, b_ih + G3,
                                pgx, Bsz * Tsz, G3, 0);
    }

    // 6) layer-1 scan
    hinit_kernel<<<Bsz * Hsz / 256, 256>>>(h0 + Bsz * Hsz, phFA, phHiA, phLoA);
    gru_scan_mma<<<NBLK, 384, SCAN_SMEM_B>>>(W_hh + (size_t)G3 * Hsz, b_hh + G3,
                                             pgx, pyHi, pyLo,
                                             phFA, phFB, phHiA, phHiB, phLoA, phLoB, Tsz);

    // 7) logits for t < T-1 (row remap skips last timestep)
    {
        int M = Bsz * (Tsz - 1);                 // 32704
        dim3 grid(Vsz / 64, (M + 127) / 128);
        mma_gemm<<<grid, 256>>>(pyHi, pyLo, W_out, b_out, out, M, Vsz, 1);
    }
}

// round 9
// speedup vs baseline: 3.8888x; 1.1818x over previous
#include <cuda_runtime.h>
#include <cuda_bf16.h>
#include <math.h>

// Problem constants
#define Bsz 64
#define Tsz 512
#define Vsz 256
#define Hsz 1024
#define G3  3072   // 3*H
#define NBLK 128

#define SWPAD 1032       // W strip row stride (bf16) -> ldmatrix conflict-free
#define CHPAD 72         // h k64-chunk row stride (bf16)
#define GHS   25
// SMEM: W hi/lo + h [2 grp][2 buf][hi/lo][64*CHPAD] + ghs[2][64*GHS]
#define SCAN_SMEM_B (24*SWPAD*2*2 + 8*64*CHPAD*2 + 2*64*GHS*4)   // 185600 B

typedef unsigned long long ull;

// ---------------- mma.sync helpers ------------------------------------------
__device__ __forceinline__ void mma_bf16(float* c, const unsigned* a, const unsigned* b) {
    asm volatile(
        "mma.sync.aligned.m16n8k16.row.col.f32.bf16.bf16.f32 "
        "{%0,%1,%2,%3}, {%4,%5,%6,%7}, {%8,%9}, {%0,%1,%2,%3};\n"
        : "+f"(c[0]), "+f"(c[1]), "+f"(c[2]), "+f"(c[3])
        : "r"(a[0]), "r"(a[1]), "r"(a[2]), "r"(a[3]), "r"(b[0]), "r"(b[1]));
}
__device__ __forceinline__ void ldsm4(unsigned* r, const void* p) {
    unsigned a = (unsigned)__cvta_generic_to_shared(p);
    asm volatile("ldmatrix.sync.aligned.m8n8.x4.shared.b16 {%0,%1,%2,%3}, [%4];"
                 : "=r"(r[0]), "=r"(r[1]), "=r"(r[2]), "=r"(r[3]) : "r"(a));
}
__device__ __forceinline__ unsigned pack_bf16x2(__nv_bfloat16 a, __nv_bfloat16 b) {
    __nv_bfloat162 t; t.x = a; t.y = b;
    return *(unsigned*)&t;
}

// packed fp32x2 FMA (kept for the fp32 M0 GEMM)
__device__ __forceinline__ void ffma2(ull& d, ull a, ull b) {
    asm("fma.rn.f32x2 %0, %1, %2, %0;" : "+l"(d) : "l"(a), "l"(b));
}
__device__ __forceinline__ ull pack_rep(float v) {
    ull r; unsigned u = __float_as_uint(v);
    asm("mov.b64 %0, {%1, %1};" : "=l"(r) : "r"(u));
    return r;
}
__device__ __forceinline__ float2 unpack2(ull v) {
    float2 r;
    asm("mov.b64 {%0, %1}, %2;" : "=f"(r.x), "=f"(r.y) : "l"(v));
    return r;
}

// ---------------- scratch (static __device__, no allocations) ----------------
__device__ float g_M0[(size_t)Vsz * G3];
__device__ float g_gx[(size_t)Bsz * Tsz * G3];
__device__ __nv_bfloat16 g_yHi[(size_t)Bsz * Tsz * Hsz];
__device__ __nv_bfloat16 g_yLo[(size_t)Bsz * Tsz * Hsz];
__device__ float g_hFA[Bsz * Hsz];
__device__ float g_hFB[Bsz * Hsz];
__device__ __nv_bfloat16 g_hHiA[Bsz * Hsz], g_hHiB[Bsz * Hsz];
__device__ __nv_bfloat16 g_hLoA[Bsz * Hsz], g_hLoB[Bsz * Hsz];
__device__ unsigned g_bar;

// ---------------- h0 init: fp32 copy + bf16 hi/lo split ----------------------
__global__ __launch_bounds__(256) void hinit_kernel(
    const float* __restrict__ src, float* __restrict__ hf,
    __nv_bfloat16* __restrict__ hhi, __nv_bfloat16* __restrict__ hlo)
{
    int i = blockIdx.x * 256 + threadIdx.x;
    float f = src[i];
    hf[i] = f;
    __nv_bfloat16 h = __float2bfloat16(f);
    hhi[i] = h;
    hlo[i] = __float2bfloat16(f - __bfloat162float(h));
}

// ---------------- fp32 GEMM 128x128x16, f32x2 (M0 only; also zeroes g_bar) ---
__global__ __launch_bounds__(256, 2) void gemm_tn_128(
    const float* __restrict__ A, const float* __restrict__ B,
    const float* __restrict__ bias, float* __restrict__ C,
    int M, int N, int K)
{
    if (blockIdx.x == 0 && blockIdx.y == 0 && threadIdx.x == 0) g_bar = 0u;

    __shared__ float As[16 * 128];
    __shared__ float Bs[16 * 128];
    const int tid = threadIdx.x;
    const int m0 = blockIdx.y * 128;
    const int n0 = blockIdx.x * 128;
    const int ty = tid >> 4;
    const int tx = tid & 15;
    const int lr = tid >> 1;
    const int lk = (tid & 1) << 3;

    const float* Ap = A + (size_t)(m0 + lr) * K + lk;
    const float* Bp = B + (size_t)(n0 + lr) * K + lk;

    ull acc[8][4];
#pragma unroll
    for (int i = 0; i < 8; ++i)
#pragma unroll
        for (int j = 0; j < 4; ++j) acc[i][j] = 0ull;

    float4 pa0 = *(const float4*)Ap;
    float4 pa1 = *(const float4*)(Ap + 4);
    float4 pb0 = *(const float4*)Bp;
    float4 pb1 = *(const float4*)(Bp + 4);

    const int nch = K >> 4;
    for (int c = 0; c < nch; ++c) {
        As[(lk + 0) * 128 + lr] = pa0.x; As[(lk + 1) * 128 + lr] = pa0.y;
        As[(lk + 2) * 128 + lr] = pa0.z; As[(lk + 3) * 128 + lr] = pa0.w;
        As[(lk + 4) * 128 + lr] = pa1.x; As[(lk + 5) * 128 + lr] = pa1.y;
        As[(lk + 6) * 128 + lr] = pa1.z; As[(lk + 7) * 128 + lr] = pa1.w;
        Bs[(lk + 0) * 128 + lr] = pb0.x; Bs[(lk + 1) * 128 + lr] = pb0.y;
        Bs[(lk + 2) * 128 + lr] = pb0.z; Bs[(lk + 3) * 128 + lr] = pb0.w;
        Bs[(lk + 4) * 128 + lr] = pb1.x; Bs[(lk + 5) * 128 + lr] = pb1.y;
        Bs[(lk + 6) * 128 + lr] = pb1.z; Bs[(lk + 7) * 128 + lr] = pb1.w;
        __syncthreads();
        if (c + 1 < nch) {
            pa0 = *(const float4*)(Ap + (c + 1) * 16);
            pa1 = *(const float4*)(Ap + (c + 1) * 16 + 4);
            pb0 = *(const float4*)(Bp + (c + 1) * 16);
            pb1 = *(const float4*)(Bp + (c + 1) * 16 + 4);
        }
#pragma unroll
        for (int k = 0; k < 16; ++k) {
            float4 a0 = *(const float4*)&As[k * 128 + (ty << 2)];
            float4 a1 = *(const float4*)&As[k * 128 + (ty << 2) + 64];
            ulonglong2 b0 = *(const ulonglong2*)&Bs[k * 128 + (tx << 2)];
            ulonglong2 b1 = *(const ulonglong2*)&Bs[k * 128 + (tx << 2) + 64];
            ull ap[8];
            ap[0] = pack_rep(a0.x); ap[1] = pack_rep(a0.y);
            ap[2] = pack_rep(a0.z); ap[3] = pack_rep(a0.w);
            ap[4] = pack_rep(a1.x); ap[5] = pack_rep(a1.y);
            ap[6] = pack_rep(a1.z); ap[7] = pack_rep(a1.w);
#pragma unroll
            for (int i = 0; i < 8; ++i) {
                ffma2(acc[i][0], ap[i], b0.x);
                ffma2(acc[i][1], ap[i], b0.y);
                ffma2(acc[i][2], ap[i], b1.x);
                ffma2(acc[i][3], ap[i], b1.y);
            }
        }
        __syncthreads();
    }

    float bb[8];
#pragma unroll
    for (int j = 0; j < 4; ++j) {
        bb[j]     = bias[n0 + (tx << 2) + j];
        bb[4 + j] = bias[n0 + (tx << 2) + 64 + j];
    }
#pragma unroll
    for (int i = 0; i < 8; ++i) {
        int row = m0 + (ty << 2) + (i & 3) + ((i >> 2) << 6);
        float* Cp = C + (size_t)row * N + n0 + (tx << 2);
        float2 c0 = unpack2(acc[i][0]);
        float2 c1 = unpack2(acc[i][1]);
        float2 c2 = unpack2(acc[i][2]);
        float2 c3 = unpack2(acc[i][3]);
        float4 v0 = make_float4(c0.x + bb[0], c0.y + bb[1], c1.x + bb[2], c1.y + bb[3]);
        float4 v1 = make_float4(c2.x + bb[4], c2.y + bb[5], c3.x + bb[6], c3.y + bb[7]);
        *(float4*)Cp = v0;
        *(float4*)(Cp + 64) = v1;
    }
}

// ---------------- gx0 gather: gx0[bt, g] = M0T[X[bt], g] ---------------------
__global__ __launch_bounds__(256) void gx0_fill_kernel(const int* __restrict__ X)
{
    size_t idx = (size_t)blockIdx.x * 256 + threadIdx.x;
    int bt = (int)(idx / (G3 / 4));
    int gq = (int)(idx % (G3 / 4));
    int tok = X[bt];
    float4 v = ((const float4*)g_M0)[(size_t)tok * (G3 / 4) + gq];
    ((float4*)g_gx)[idx] = v;
}

// ---------------- bf16-split MMA GEMM: C[M,N] = Y @ B^T + bias ---------------
__global__ __launch_bounds__(256) void mma_gemm(
    const __nv_bfloat16* __restrict__ Ahi, const __nv_bfloat16* __restrict__ Alo,
    const float* __restrict__ B, const float* __restrict__ bias,
    float* __restrict__ C, int M, int N, int remapA)
{
    __shared__ __nv_bfloat16 sAhi[128 * 40], sAlo[128 * 40];
    __shared__ __nv_bfloat16 sBhi[64 * 40],  sBlo[64 * 40];
    const int tid = threadIdx.x, wid = tid >> 5, lane = tid & 31;
    const int m0 = blockIdx.y * 128, n0 = blockIdx.x * 64;
    const int wm = wid & 3, wn = wid >> 2;

    float acc[2][4][4];
#pragma unroll
    for (int mt = 0; mt < 2; ++mt)
#pragma unroll
        for (int nt = 0; nt < 4; ++nt)
#pragma unroll
            for (int q = 0; q < 4; ++q) acc[mt][nt][q] = 0.f;

    for (int c = 0; c < 32; ++c) {
        const int k0 = c * 32;
#pragma unroll
        for (int s = 0; s < 4; ++s) {
            int i = tid + s * 256;
            int arr = i >> 9, e = i & 511, row = e >> 2, q = e & 3;
            int r = m0 + row; if (r >= M) r = M - 1;
            if (remapA) r = (r / (Tsz - 1)) * Tsz + (r % (Tsz - 1));
            const __nv_bfloat16* src = arr ? Alo : Ahi;
            uint4 v = *(const uint4*)(src + (size_t)r * Hsz + k0 + q * 8);
            __nv_bfloat16* dst = (arr ? sAlo : sAhi) + row * 40 + q * 8;
            *(uint4*)dst = v;
        }
#pragma unroll
        for (int s = 0; s < 2; ++s) {
            int i = tid + s * 256;
            int row = i >> 3, q = i & 7;
            float4 v = *(const float4*)(B + (size_t)(n0 + row) * Hsz + k0 + q * 4);
            __nv_bfloat16 h0 = __float2bfloat16(v.x), h1 = __float2bfloat16(v.y);
            __nv_bfloat16 h2 = __float2bfloat16(v.z), h3 = __float2bfloat16(v.w);
            __nv_bfloat16 l0 = __float2bfloat16(v.x - __bfloat162float(h0));
            __nv_bfloat16 l1 = __float2bfloat16(v.y - __bfloat162float(h1));
            __nv_bfloat16 l2 = __float2bfloat16(v.z - __bfloat162float(h2));
            __nv_bfloat16 l3 = __float2bfloat16(v.w - __bfloat162float(h3));
            unsigned* dh = (unsigned*)(sBhi + row * 40 + q * 4);
            dh[0] = pack_bf16x2(h0, h1); dh[1] = pack_bf16x2(h2, h3);
            unsigned* dl = (unsigned*)(sBlo + row * 40 + q * 4);
            dl[0] = pack_bf16x2(l0, l1); dl[1] = pack_bf16x2(l2, l3);
        }
        __syncthreads();

        unsigned bh[4][4], bl[4][4];
#pragma unroll
        for (int nt = 0; nt < 4; ++nt) {
            const int brow = wn * 32 + nt * 8 + (lane & 7);
            ldsm4(bh[nt], sBhi + brow * 40 + ((lane >> 3) << 3));
            ldsm4(bl[nt], sBlo + brow * 40 + ((lane >> 3) << 3));
        }
#pragma unroll
        for (int kk = 0; kk < 2; ++kk) {
            unsigned ah[2][4], al[2][4];
#pragma unroll
            for (int mt = 0; mt < 2; ++mt) {
                const int aoff = (wm * 32 + mt * 16 + (lane & 15)) * 40 + kk * 16 + ((lane >> 4) << 3);
                ldsm4(ah[mt], sAhi + aoff);
                ldsm4(al[mt], sAlo + aoff);
            }
#pragma unroll
            for (int mt = 0; mt < 2; ++mt)
#pragma unroll
                for (int nt = 0; nt < 4; ++nt) {
                    mma_bf16(acc[mt][nt], ah[mt], bh[nt] + 2 * kk);
                    mma_bf16(acc[mt][nt], ah[mt], bl[nt] + 2 * kk);
                    mma_bf16(acc[mt][nt], al[mt], bh[nt] + 2 * kk);
                }
        }
        __syncthreads();
    }

#pragma unroll
    for (int mt = 0; mt < 2; ++mt)
#pragma unroll
        for (int nt = 0; nt < 4; ++nt) {
            int r0 = m0 + wm * 32 + mt * 16 + (lane >> 2);
            int cb = n0 + wn * 32 + nt * 8 + 2 * (lane & 3);
            float b0 = bias[cb], b1 = bias[cb + 1];
            if (r0 < M) {
                C[(size_t)r0 * N + cb]     = acc[mt][nt][0] + b0;
                C[(size_t)r0 * N + cb + 1] = acc[mt][nt][1] + b1;
            }
            int r1 = r0 + 8;
            if (r1 < M) {
                C[(size_t)r1 * N + cb]     = acc[mt][nt][2] + b0;
                C[(size_t)r1 * N + cb + 1] = acc[mt][nt][3] + b1;
            }
        }
}

// ---------------- persistent GRU scan (gate-shared, k-split, bf16 MMA) -------
// 256 threads, 8 warps = 4 m-tiles x 2 k-halves. Each warp computes ALL 3
// gates for its m16 over k512 -> A fragments loaded once, W fragments twice.
// ghs[2] partials summed in the gate phase.
__global__ __launch_bounds__(256) void gru_scan_mma(
    const float* __restrict__ Whh, const float* __restrict__ bhh,
    const float* __restrict__ gx,
    __nv_bfloat16* __restrict__ yHi, __nv_bfloat16* __restrict__ yLo,
    float* __restrict__ hfA, float* __restrict__ hfB,
    __nv_bfloat16* __restrict__ hHiA, __nv_bfloat16* __restrict__ hHiB,
    __nv_bfloat16* __restrict__ hLoA, __nv_bfloat16* __restrict__ hLoB,
    int t_base)
{
    extern __shared__ __align__(16) unsigned char smraw[];
    __nv_bfloat16* sWhi = (__nv_bfloat16*)smraw;            // [24][SWPAD]
    __nv_bfloat16* sWlo = sWhi + 24 * SWPAD;
    __nv_bfloat16* sH   = sWlo + 24 * SWPAD;                // [grp][buf][hi/lo][64*CHPAD]
    float* ghs = (float*)(sH + 8 * 64 * CHPAD);             // [2][64*GHS]

    const int tid = threadIdx.x, wid = tid >> 5, lane = tid & 31;
    const int c0 = blockIdx.x << 3;
    const int mw = wid & 3, kc = wid >> 2;
    const int gtid = tid & 127, grp = tid >> 7;             // staging group == kc

    // Convert W strip to bf16 hi/lo in SMEM once per layer.
    for (int i = tid; i < 24 * 1024; i += 256) {
        int r = i >> 10, k = i & 1023;
        int g = r >> 3, jj = r & 7;
        float f = Whh[(size_t)(g * Hsz + c0 + jj) * Hsz + k];
        __nv_bfloat16 h = __float2bfloat16(f);
        sWhi[r * SWPAD + k] = h;
        sWlo[r * SWPAD + k] = __float2bfloat16(f - __bfloat162float(h));
    }
    const int gy = tid >> 3, gxc = tid & 7;
    const int jcol = c0 + gxc;
    const float br = bhh[jcol];
    const float bz = bhh[Hsz + jcol];
    const float bn = bhh[2 * Hsz + jcol];
    __syncthreads();

    for (int t = 0; t < Tsz; ++t) {
        const int par = t & 1;
        const float* hfIn  = par ? hfB : hfA;
        float*       hfOut = par ? hfA : hfB;
        const __nv_bfloat16* hHiIn = par ? hHiB : hHiA;
        const __nv_bfloat16* hLoIn = par ? hLoB : hLoA;
        __nv_bfloat16* hHiOut = par ? hHiA : hHiB;
        __nv_bfloat16* hLoOut = par ? hLoA : hLoB;

        uint4 stg[8];
        // stage chunk 0 of this thread's k-group (k64)
#pragma unroll
        for (int s = 0; s < 8; ++s) {
            int idx = gtid + s * 128;                 // 0..1023
            int arr = idx >> 9, e = idx & 511, row = e >> 3, q = e & 7;
            const __nv_bfloat16* src = arr ? hLoIn : hHiIn;
            stg[s] = __ldcg((const uint4*)(src + (size_t)row * Hsz + grp * 512) + q);
        }
        // prefetch gate preacts + h_old
        float pxr[2], pxz[2], pxn[2], phold[2];
#pragma unroll
        for (int r = 0; r < 2; ++r) {
            const int b = gy + (r << 5);
            const float* gxr = gx + ((size_t)b * Tsz + t) * G3;
            pxr[r] = __ldcg(gxr + jcol);
            pxz[r] = __ldcg(gxr + Hsz + jcol);
            pxn[r] = __ldcg(gxr + 2 * Hsz + jcol);
            phold[r] = hfIn[(size_t)b * Hsz + jcol];
        }
#pragma unroll
        for (int s = 0; s < 8; ++s) {
            int idx = gtid + s * 128;
            int arr = idx >> 9, e = idx & 511, row = e >> 3, q = e & 7;
            __nv_bfloat16* dst = sH + ((grp * 2 + 0) * 2 + arr) * 64 * CHPAD + row * CHPAD + q * 8;
            *(uint4*)dst = stg[s];
        }
        __syncthreads();

        float accP[3][4], accQ[3][4];
#pragma unroll
        for (int g = 0; g < 3; ++g)
#pragma unroll
            for (int q = 0; q < 4; ++q) { accP[g][q] = 0.f; accQ[g][q] = 0.f; }

        for (int it = 0; it < 8; ++it) {
            if (it < 7) {
#pragma unroll
                for (int s = 0; s < 8; ++s) {
                    int idx = gtid + s * 128;
                    int arr = idx >> 9, e = idx & 511, row = e >> 3, q = e & 7;
                    const __nv_bfloat16* src = arr ? hLoIn : hHiIn;
                    stg[s] = __ldcg((const uint4*)(src + (size_t)row * Hsz + grp * 512 + (it + 1) * 64) + q);
                }
            }
            const __nv_bfloat16* Hh = sH + ((kc * 2 + (it & 1)) * 2 + 0) * 64 * CHPAD;
            const __nv_bfloat16* Hl = sH + ((kc * 2 + (it & 1)) * 2 + 1) * 64 * CHPAD;
#pragma unroll
            for (int kt = 0; kt < 2; ++kt) {
                const int kabs = kc * 512 + it * 64 + kt * 32;
                unsigned bh[3][4], bl[3][4];
#pragma unroll
                for (int g = 0; g < 3; ++g) {
                    const int woff = (g * 8 + (lane & 7)) * SWPAD + kabs + ((lane >> 3) << 3);
                    ldsm4(bh[g], sWhi + woff);
                    ldsm4(bl[g], sWlo + woff);
                }
#pragma unroll
                for (int kk = 0; kk < 2; ++kk) {
                    unsigned ah[4], al[4];
                    const int aoff = (mw * 16 + (lane & 15)) * CHPAD + kt * 32 + kk * 16 + ((lane >> 4) << 3);
                    ldsm4(ah, Hh + aoff);
                    ldsm4(al, Hl + aoff);
#pragma unroll
                    for (int g = 0; g < 3; ++g) {
                        mma_bf16(accP[g], ah, bh[g] + 2 * kk);
                        mma_bf16(accQ[g], ah, bl[g] + 2 * kk);
                        mma_bf16(accQ[g], al, bh[g] + 2 * kk);
                    }
                }
            }
            if (it < 7) {
#pragma unroll
                for (int s = 0; s < 8; ++s) {
                    int idx = gtid + s * 128;
                    int arr = idx >> 9, e = idx & 511, row = e >> 3, q = e & 7;
                    __nv_bfloat16* dst = sH + ((grp * 2 + ((it + 1) & 1)) * 2 + arr) * 64 * CHPAD
                                       + row * CHPAD + q * 8;
                    *(uint4*)dst = stg[s];
                }
            }
            __syncthreads();
        }

        // write k-partial gh preacts to SMEM
        {
            float* gp = ghs + kc * 64 * GHS;
            int row = mw * 16 + (lane >> 2);
#pragma unroll
            for (int g = 0; g < 3; ++g) {
                int gcol = g * 8 + 2 * (lane & 3);
                gp[row * GHS + gcol]           = accP[g][0] + accQ[g][0];
                gp[row * GHS + gcol + 1]       = accP[g][1] + accQ[g][1];
                gp[(row + 8) * GHS + gcol]     = accP[g][2] + accQ[g][2];
                gp[(row + 8) * GHS + gcol + 1] = accP[g][3] + accQ[g][3];
            }
        }
        __syncthreads();

        // gates + state update (all 256 threads)
        {
            const float* g0 = ghs;
            const float* g1 = ghs + 64 * GHS;
#pragma unroll
            for (int r = 0; r < 2; ++r) {
                const int b = gy + (r << 5);
                const float a0 = g0[b * GHS + gxc]      + g1[b * GHS + gxc];
                const float a1 = g0[b * GHS + 8 + gxc]  + g1[b * GHS + 8 + gxc];
                const float a2 = g0[b * GHS + 16 + gxc] + g1[b * GHS + 16 + gxc];
                const size_t rowbt = (size_t)b * Tsz + t;
                const float rg = 1.0f / (1.0f + expf(-(pxr[r] + a0 + br)));
                const float zg = 1.0f / (1.0f + expf(-(pxz[r] + a1 + bz)));
                const float ng = tanhf(pxn[r] + rg * (a2 + bn));
                const float hnew = (1.0f - zg) * ng + zg * phold[r];
                hfOut[(size_t)b * Hsz + jcol] = hnew;
                __nv_bfloat16 hh = __float2bfloat16(hnew);
                __nv_bfloat16 hl = __float2bfloat16(hnew - __bfloat162float(hh));
                hHiOut[(size_t)b * Hsz + jcol] = hh;
                hLoOut[(size_t)b * Hsz + jcol] = hl;
                yHi[rowbt * Hsz + jcol] = hh;
                yLo[rowbt * Hsz + jcol] = hl;
            }
        }

        // ---- grid barrier ----
        __syncthreads();
        if (tid == 0) {
            __threadfence();
            atomicAdd(&g_bar, 1u);
            const unsigned target = (unsigned)NBLK * (unsigned)(t_base + t + 1);
            unsigned v;
            do {
                asm volatile("ld.global.acquire.gpu.u32 %0, [%1];"
                             : "=r"(v) : "l"(&g_bar));
            } while (v < target);
        }
        __syncthreads();
    }
}

// ---------------- launch ------------------------------------------------------
extern "C" void kernel_launch(void* const* d_in, const int* in_sizes, int n_in,
                              void* d_out, int out_size)
{
    const int*   X     = (const int*)d_in[0];
    const float* h0    = (const float*)d_in[1];
    const float* emb   = (const float*)d_in[2];
    const float* W_ih  = (const float*)d_in[3];
    const float* W_hh  = (const float*)d_in[4];
    const float* b_ih  = (const float*)d_in[5];
    const float* b_hh  = (const float*)d_in[6];
    const float* W_out = (const float*)d_in[7];
    const float* b_out = (const float*)d_in[8];
    float* out = (float*)d_out;

    float *pM0, *pgx, *phFA, *phFB;
    __nv_bfloat16 *pyHi, *pyLo, *phHiA, *phHiB, *phLoA, *phLoB;
    cudaGetSymbolAddress((void**)&pM0,  g_M0);
    cudaGetSymbolAddress((void**)&pgx,  g_gx);
    cudaGetSymbolAddress((void**)&pyHi, g_yHi);
    cudaGetSymbolAddress((void**)&pyLo, g_yLo);
    cudaGetSymbolAddress((void**)&phFA, g_hFA);
    cudaGetSymbolAddress((void**)&phFB, g_hFB);
    cudaGetSymbolAddress((void**)&phHiA, g_hHiA);
    cudaGetSymbolAddress((void**)&phHiB, g_hHiB);
    cudaGetSymbolAddress((void**)&phLoA, g_hLoA);
    cudaGetSymbolAddress((void**)&phLoB, g_hLoB);

    cudaFuncSetAttribute(gru_scan_mma,
                         cudaFuncAttributeMaxDynamicSharedMemorySize, SCAN_SMEM_B);

    // 1) h0 split for layer 0
    hinit_kernel<<<Bsz * Hsz / 256, 256>>>(h0, phFA, phHiA, phLoA);

    // 2) M0T[v,g] = emb[v].W_ih0[g] + b_ih0[g]  (also zeroes grid barrier)
    {
        dim3 grid(G3 / 128, Vsz / 128);
        gemm_tn_128<<<grid, 256>>>(emb, W_ih, b_ih, pM0, Vsz, G3, Hsz);
    }

    // 3) gx0 gather
    gx0_fill_kernel<<<(Bsz * Tsz * (G3 / 4)) / 256, 256>>>(X);

    // 4) layer-0 scan  (4th launch -> ncu capture slot)
    gru_scan_mma<<<NBLK, 256, SCAN_SMEM_B>>>(W_hh, b_hh, pgx, pyHi, pyLo,
                                             phFA, phFB, phHiA, phHiB, phLoA, phLoB, 0);

    // 5) gx1 = y0 @ W_ih1^T + b_ih1
    {
        dim3 grid(G3 / 64, (Bsz * Tsz) / 128);
        mma_gemm<<<grid, 256>>>(pyHi, pyLo, W_ih + (size_t)G3 * Hsz, b_ih + G3,
                                pgx, Bsz * Tsz, G3, 0);
    }

    // 6) layer-1 scan
    hinit_kernel<<<Bsz * Hsz / 256, 256>>>(h0 + Bsz * Hsz, phFA, phHiA, phLoA);
    gru_scan_mma<<<NBLK, 256, SCAN_SMEM_B>>>(W_hh + (size_t)G3 * Hsz, b_hh + G3,
                                             pgx, pyHi, pyLo,
                                             phFA, phFB, phHiA, phHiB, phLoA, phLoB, Tsz);

    // 7) logits for t < T-1 (row remap skips last timestep)
    {
        int M = Bsz * (Tsz - 1);                 // 32704
        dim3 grid(Vsz / 64, (M + 127) / 128);
        mma_gemm<<<grid, 256>>>(pyHi, pyLo, W_out, b_out, out, M, Vsz, 1);
    }
}